// round 1
// baseline (speedup 1.0000x reference)
#include <cuda_runtime.h>

#define NB 8
#define TQ 512
#define TK 1024
#define NH 16
#define DH 64
#define DD 1024
#define ATT_SCALE 0.015625f   // H/D = 16/1024

// ---------------- device scratch (no allocations allowed) ----------------
__device__ float g_Qh[NB * NH * TQ * DH];   // 16 MB  [n,h,t,e]
__device__ float g_Kh[NB * NH * TK * DH];   // 32 MB  [n,h,k,e]
__device__ float g_Vh[NB * NH * TK * DH];   // 32 MB  [n,h,k,e]
__device__ float g_attO[NB * TQ * DD];      // 16 MB  [n,t,d] with d = h*64+e

// =========================================================================
// proj_q: qf[n,t,d] = sum_c q[n,c,t] * Wq[d,c] + bq[d]
// A is stored (c,t): A[c*TQ + t].  Tile 64x64, K-tile 16, 4x4 per thread.
// Store head-major into g_Qh.
// =========================================================================
__global__ __launch_bounds__(256) void proj_q_kernel(
    const float* __restrict__ q, const float* __restrict__ Wq,
    const float* __restrict__ bq) {
    const int nb = blockIdx.z;
    const int d0 = blockIdx.x * 64;
    const int t0 = blockIdx.y * 64;
    const float* A = q + (size_t)nb * DD * TQ;

    __shared__ float As[16][64];   // [c_local][t_local]
    __shared__ float Bs[16][68];   // [c_local][d_local] (padded)

    const int tid = threadIdx.x;
    const int tx = tid & 15, ty = tid >> 4;

    float acc[4][4];
#pragma unroll
    for (int r = 0; r < 4; r++)
#pragma unroll
        for (int i = 0; i < 4; i++) acc[r][i] = 0.f;

    for (int c0 = 0; c0 < DD; c0 += 16) {
#pragma unroll
        for (int u = 0; u < 4; u++) {
            int idx = tid + u * 256;
            As[idx >> 6][idx & 63] = A[(size_t)(c0 + (idx >> 6)) * TQ + t0 + (idx & 63)];
        }
#pragma unroll
        for (int u = 0; u < 4; u++) {
            int idx = tid + u * 256;
            Bs[idx & 15][idx >> 4] = Wq[(size_t)(d0 + (idx >> 4)) * DD + c0 + (idx & 15)];
        }
        __syncthreads();
#pragma unroll
        for (int kk = 0; kk < 16; kk++) {
            float a[4], b[4];
#pragma unroll
            for (int r = 0; r < 4; r++) a[r] = As[kk][ty * 4 + r];
#pragma unroll
            for (int i = 0; i < 4; i++) b[i] = Bs[kk][tx * 4 + i];
#pragma unroll
            for (int r = 0; r < 4; r++)
#pragma unroll
                for (int i = 0; i < 4; i++) acc[r][i] += a[r] * b[i];
        }
        __syncthreads();
    }

    // d = h*64 + e for Q heads
    const int h = d0 >> 6;
    float4 bv = *(const float4*)&bq[d0 + tx * 4];
    float* dst = g_Qh + ((size_t)(nb * NH + h) * TQ + t0) * DH;
#pragma unroll
    for (int r = 0; r < 4; r++) {
        float4 v = make_float4(acc[r][0] + bv.x, acc[r][1] + bv.y,
                               acc[r][2] + bv.z, acc[r][3] + bv.w);
        *(float4*)&dst[(ty * 4 + r) * DH + tx * 4] = v;
    }
}

// =========================================================================
// proj_kv: kvf[n,t,d] = sum_c kv[n,c,t] * Wkv[d,c] + bkv[d],  d in [0,2048)
// Head interleave: d = h*128 + e;  e<64 -> K, e>=64 -> V (e-64).
// Each 64-wide d-tile lands entirely in one head's K or V half.
// =========================================================================
__global__ __launch_bounds__(256) void proj_kv_kernel(
    const float* __restrict__ kv, const float* __restrict__ Wkv,
    const float* __restrict__ bkv) {
    const int nb = blockIdx.z;
    const int d0 = blockIdx.x * 64;
    const int t0 = blockIdx.y * 64;
    const float* A = kv + (size_t)nb * DD * TK;

    __shared__ float As[16][64];
    __shared__ float Bs[16][68];

    const int tid = threadIdx.x;
    const int tx = tid & 15, ty = tid >> 4;

    float acc[4][4];
#pragma unroll
    for (int r = 0; r < 4; r++)
#pragma unroll
        for (int i = 0; i < 4; i++) acc[r][i] = 0.f;

    for (int c0 = 0; c0 < DD; c0 += 16) {
#pragma unroll
        for (int u = 0; u < 4; u++) {
            int idx = tid + u * 256;
            As[idx >> 6][idx & 63] = A[(size_t)(c0 + (idx >> 6)) * TK + t0 + (idx & 63)];
        }
#pragma unroll
        for (int u = 0; u < 4; u++) {
            int idx = tid + u * 256;
            Bs[idx & 15][idx >> 4] = Wkv[(size_t)(d0 + (idx >> 4)) * DD + c0 + (idx & 15)];
        }
        __syncthreads();
#pragma unroll
        for (int kk = 0; kk < 16; kk++) {
            float a[4], b[4];
#pragma unroll
            for (int r = 0; r < 4; r++) a[r] = As[kk][ty * 4 + r];
#pragma unroll
            for (int i = 0; i < 4; i++) b[i] = Bs[kk][tx * 4 + i];
#pragma unroll
            for (int r = 0; r < 4; r++)
#pragma unroll
                for (int i = 0; i < 4; i++) acc[r][i] += a[r] * b[i];
        }
        __syncthreads();
    }

    const int h = d0 >> 7;
    const bool isV = (d0 & 64) != 0;
    float4 bv = *(const float4*)&bkv[d0 + tx * 4];
    float* dst = (isV ? g_Vh : g_Kh) + ((size_t)(nb * NH + h) * TK + t0) * DH;
#pragma unroll
    for (int r = 0; r < 4; r++) {
        float4 v = make_float4(acc[r][0] + bv.x, acc[r][1] + bv.y,
                               acc[r][2] + bv.z, acc[r][3] + bv.w);
        *(float4*)&dst[(ty * 4 + r) * DH + tx * 4] = v;
    }
}

// =========================================================================
// Flash attention, fp32. Block = 64 q-rows of one (n,h); loops over k tiles
// of 64 up to kv_len (skips fully-masked tiles). Online softmax, P staged
// in smem, K smem buffer reused for V.
// dyn smem: Qs 64*64 | KV 64*65 | Ss 64*64  = 49408 bytes
// =========================================================================
__global__ __launch_bounds__(256) void attn_kernel(const int* __restrict__ kv_len) {
    extern __shared__ float sm[];
    float* Qs = sm;                        // 64*64, [t][e]
    float* KV = sm + 64 * 64;              // 64*65: K phase [e][j] (padded), V phase [j][e]
    float* Ss = sm + 64 * 64 + 64 * 65;    // 64*64, P tile [t][j]

    const int bh = blockIdx.y;             // n*16 + h
    const int nb = bh >> 4;
    const int t0 = blockIdx.x * 64;
    const int len = kv_len[nb];

    const float* Qg = g_Qh + ((size_t)bh * TQ + t0) * DH;
    const float* Kg = g_Kh + (size_t)bh * TK * DH;
    const float* Vg = g_Vh + (size_t)bh * TK * DH;

    const int tid = threadIdx.x;
    const int tx = tid & 15, ty = tid >> 4;

#pragma unroll
    for (int u = 0; u < 16; u++) {
        int idx = tid + u * 256;
        Qs[idx] = Qg[idx];
    }

    float m[4], l[4], acc[4][4];
#pragma unroll
    for (int r = 0; r < 4; r++) {
        m[r] = -1e30f;
        l[r] = 0.f;
#pragma unroll
        for (int i = 0; i < 4; i++) acc[r][i] = 0.f;
    }

    const int ktiles = (len + 63) >> 6;
    for (int kt = 0; kt < ktiles; kt++) {
        const int k0 = kt * 64;
        __syncthreads();  // protect KV reuse (covers Qs on first iter too)
        // K tile, transposed into smem: KV[e*65 + j] = K[k0+j][e]
#pragma unroll
        for (int u = 0; u < 16; u++) {
            int idx = tid + u * 256;
            int j = idx >> 6, dd = idx & 63;
            KV[dd * 65 + j] = Kg[(size_t)(k0 + j) * DH + dd];
        }
        __syncthreads();

        float s[4][4];
#pragma unroll
        for (int r = 0; r < 4; r++)
#pragma unroll
            for (int i = 0; i < 4; i++) s[r][i] = 0.f;
#pragma unroll
        for (int kk = 0; kk < 64; kk++) {
            float a[4], b[4];
#pragma unroll
            for (int r = 0; r < 4; r++) a[r] = Qs[(ty * 4 + r) * 64 + kk];
#pragma unroll
            for (int i = 0; i < 4; i++) b[i] = KV[kk * 65 + tx * 4 + i];
#pragma unroll
            for (int r = 0; r < 4; r++)
#pragma unroll
                for (int i = 0; i < 4; i++) s[r][i] += a[r] * b[i];
        }
        // scale + mask
#pragma unroll
        for (int r = 0; r < 4; r++)
#pragma unroll
            for (int i = 0; i < 4; i++) {
                int kg = k0 + tx * 4 + i;
                s[r][i] = (kg < len) ? s[r][i] * ATT_SCALE : -1e30f;
            }
        // online softmax update (per-row, redundantly on all 16 tx lanes)
#pragma unroll
        for (int r = 0; r < 4; r++) {
            float tm = fmaxf(fmaxf(s[r][0], s[r][1]), fmaxf(s[r][2], s[r][3]));
#pragma unroll
            for (int o = 8; o > 0; o >>= 1)
                tm = fmaxf(tm, __shfl_xor_sync(0xffffffffu, tm, o, 16));
            float mn = fmaxf(m[r], tm);
            float scl = __expf(m[r] - mn);
            m[r] = mn;
            float ssum = 0.f;
#pragma unroll
            for (int i = 0; i < 4; i++) {
                float p = __expf(s[r][i] - mn);
                s[r][i] = p;
                ssum += p;
            }
#pragma unroll
            for (int o = 8; o > 0; o >>= 1)
                ssum += __shfl_xor_sync(0xffffffffu, ssum, o, 16);
            l[r] = l[r] * scl + ssum;
#pragma unroll
            for (int i = 0; i < 4; i++) acc[r][i] *= scl;
#pragma unroll
            for (int i = 0; i < 4; i++)
                Ss[(ty * 4 + r) * 64 + tx * 4 + i] = s[r][i];
        }
        __syncthreads();  // all reads of K done, P written
        // V tile, natural layout: KV[j*65 + e] = V[k0+j][e]
#pragma unroll
        for (int u = 0; u < 16; u++) {
            int idx = tid + u * 256;
            int j = idx >> 6, dd = idx & 63;
            KV[j * 65 + dd] = Vg[(size_t)(k0 + j) * DH + dd];
        }
        __syncthreads();
        // O += P @ V
#pragma unroll
        for (int jj = 0; jj < 64; jj++) {
            float a[4], b[4];
#pragma unroll
            for (int r = 0; r < 4; r++) a[r] = Ss[(ty * 4 + r) * 64 + jj];
#pragma unroll
            for (int i = 0; i < 4; i++) b[i] = KV[jj * 65 + tx * 4 + i];
#pragma unroll
            for (int r = 0; r < 4; r++)
#pragma unroll
                for (int i = 0; i < 4; i++) acc[r][i] += a[r] * b[i];
        }
    }

    // normalize and store: attO[n][t][h*64 + e]
    const int h = bh & 15;
    float* dst = g_attO + ((size_t)nb * TQ + t0) * DD + h * DH;
#pragma unroll
    for (int r = 0; r < 4; r++) {
        float inv = 1.0f / l[r];
        float4 v = make_float4(acc[r][0] * inv, acc[r][1] * inv,
                               acc[r][2] * inv, acc[r][3] * inv);
        *(float4*)&dst[(size_t)(ty * 4 + r) * DD + tx * 4] = v;
    }
}

// =========================================================================
// fc: out[n,o,t] = sum_d attO[n,t,d] * Wfc[o,d] + bfc[o]
// A is row-major (t,d). Output transposed through smem for coalesced stores.
// =========================================================================
__global__ __launch_bounds__(256) void fc_kernel(
    const float* __restrict__ Wfc, const float* __restrict__ bfc,
    float* __restrict__ out) {
    const int nb = blockIdx.z;
    const int o0 = blockIdx.x * 64;
    const int t0 = blockIdx.y * 64;
    const float* A = g_attO + (size_t)nb * TQ * DD;

    __shared__ float As[64][17];   // [t_local][d_local]
    __shared__ float Bs[16][68];   // [d_local][o_local]
    __shared__ float Cs[64][65];   // [o_local][t_local]

    const int tid = threadIdx.x;
    const int tx = tid & 15, ty = tid >> 4;

    float acc[4][4];
#pragma unroll
    for (int r = 0; r < 4; r++)
#pragma unroll
        for (int i = 0; i < 4; i++) acc[r][i] = 0.f;

    for (int c0 = 0; c0 < DD; c0 += 16) {
#pragma unroll
        for (int u = 0; u < 4; u++) {
            int idx = tid + u * 256;
            As[idx >> 4][idx & 15] = A[(size_t)(t0 + (idx >> 4)) * DD + c0 + (idx & 15)];
        }
#pragma unroll
        for (int u = 0; u < 4; u++) {
            int idx = tid + u * 256;
            Bs[idx & 15][idx >> 4] = Wfc[(size_t)(o0 + (idx >> 4)) * DD + c0 + (idx & 15)];
        }
        __syncthreads();
#pragma unroll
        for (int kk = 0; kk < 16; kk++) {
            float a[4], b[4];
#pragma unroll
            for (int r = 0; r < 4; r++) a[r] = As[ty * 4 + r][kk];
#pragma unroll
            for (int i = 0; i < 4; i++) b[i] = Bs[kk][tx * 4 + i];
#pragma unroll
            for (int r = 0; r < 4; r++)
#pragma unroll
                for (int i = 0; i < 4; i++) acc[r][i] += a[r] * b[i];
        }
        __syncthreads();
    }

    // stage transposed with bias, then coalesced store of out[n][o][t]
#pragma unroll
    for (int i = 0; i < 4; i++) {
        float bias = bfc[o0 + tx * 4 + i];
#pragma unroll
        for (int r = 0; r < 4; r++)
            Cs[tx * 4 + i][ty * 4 + r] = acc[r][i] + bias;
    }
    __syncthreads();
#pragma unroll
    for (int u = 0; u < 16; u++) {
        int idx = tid + u * 256;
        int ol = idx >> 6, tl = idx & 63;
        out[((size_t)nb * DD + o0 + ol) * TQ + t0 + tl] = Cs[ol][tl];
    }
}

// =========================================================================
extern "C" void kernel_launch(void* const* d_in, const int* in_sizes, int n_in,
                              void* d_out, int out_size) {
    const float* q   = (const float*)d_in[0];
    const float* kv  = (const float*)d_in[1];
    const int*   kvl = (const int*)d_in[2];
    const float* Wq  = (const float*)d_in[3];
    const float* bq  = (const float*)d_in[4];
    const float* Wkv = (const float*)d_in[5];
    const float* bkv = (const float*)d_in[6];
    const float* Wfc = (const float*)d_in[7];
    const float* bfc = (const float*)d_in[8];
    float* out = (float*)d_out;

    // attn kernel uses 49408 B dynamic smem (> 48KB default) — opt in every call
    cudaFuncSetAttribute(attn_kernel,
                         cudaFuncAttributeMaxDynamicSharedMemorySize, 49408);

    proj_q_kernel<<<dim3(16, 8, NB), 256>>>(q, Wq, bq);
    proj_kv_kernel<<<dim3(32, 16, NB), 256>>>(kv, Wkv, bkv);
    attn_kernel<<<dim3(8, NB * NH), 256, 49408>>>(kvl);
    fc_kernel<<<dim3(16, 8, NB), 256>>>(Wfc, bfc, out);
}

// round 3
// speedup vs baseline: 2.6245x; 2.6245x over previous
#include <cuda_runtime.h>
#include <cstdint>

#define NB 8
#define TQ 512
#define TKK 1024
#define NH 16
#define DH 64
#define DD 1024
#define ATT_SCALE 0.015625f   // H/D = 16/1024

// ---------------- device scratch (no allocations allowed) ----------------
__device__ float g_Qh[NB * NH * TQ * DH];   // [n,h,t,e]
__device__ float g_Kh[NB * NH * TKK * DH];  // [n,h,k,e]
__device__ float g_Vh[NB * NH * TKK * DH];  // [n,h,k,e]
__device__ float g_attO[NB * TQ * DD];      // [n,t,d], d = h*64+e

// ---------------- helpers ----------------
__device__ __forceinline__ uint32_t f2tf(float f) {
    uint32_t u;
    asm("cvt.rna.tf32.f32 %0, %1;" : "=r"(u) : "f"(f));
    return u;
}

#define MMA_TF32(d, a0, a1, a2, a3, b0, b1)                                   \
    asm volatile(                                                             \
        "mma.sync.aligned.m16n8k8.row.col.f32.tf32.tf32.f32 "                 \
        "{%0,%1,%2,%3}, {%4,%5,%6,%7}, {%8,%9}, {%0,%1,%2,%3};\n"             \
        : "+f"(d[0]), "+f"(d[1]), "+f"(d[2]), "+f"(d[3])                      \
        : "r"(a0), "r"(a1), "r"(a2), "r"(a3), "r"(b0), "r"(b1))

// smem row pitches (in 4B words) chosen for conflict-free fragment loads:
//  A/B tiles at pitch 136: bank = (8k + m) mod 32, distinct for k<4,m<8.
#define LDAB 136

// =========================================================================
// Projection GEMM: C[t, d] = sum_c act[c, t] * W[d, c]    (M = t, N = d)
// Block tile 128(t) x 64(d), BK = 16, 256 threads = 8 warps (4m x 2n),
// warp tile 32x32 = 2 m-frag x 4 n-frag of m16n8k8.
// =========================================================================
template <int TDIM, int MODE>  // MODE 0: Q heads (d=h*64+e). MODE 1: KV (d=h*128+e)
__global__ __launch_bounds__(256) void proj_mma_kernel(
    const float* __restrict__ act, const float* __restrict__ W,
    const float* __restrict__ bias) {
    __shared__ uint32_t As[16 * LDAB];   // [k][m=t]
    __shared__ uint32_t Bs[16 * LDAB];   // [k][n=d]

    const int nb = blockIdx.z;
    const int t0 = blockIdx.x * 128;
    const int d0 = blockIdx.y * 64;
    const float* A = act + (size_t)nb * DD * TDIM;

    const int tid = threadIdx.x;
    const int wid = tid >> 5, lane = tid & 31;
    const int gr = lane >> 2, tig = lane & 3;
    const int warp_m = wid >> 1, warp_n = wid & 1;

    float acc[2][4][4];
#pragma unroll
    for (int mt = 0; mt < 2; mt++)
#pragma unroll
        for (int nt = 0; nt < 4; nt++)
#pragma unroll
            for (int i = 0; i < 4; i++) acc[mt][nt][i] = 0.f;

    const int bn = tid >> 2;            // 0..63  (B loader: n index)
    const int bk4 = (tid & 3) * 4;      // 0,4,8,12

    for (int c0 = 0; c0 < DD; c0 += 16) {
        // A tile: As[k][m] = act[c0+k][t0+m], contiguous float4 in t
#pragma unroll
        for (int u = 0; u < 2; u++) {
            int lin = tid + u * 256;
            int k = lin >> 5, m4 = lin & 31;
            const float4 g = *(const float4*)(A + (size_t)(c0 + k) * TDIM + t0 + m4 * 4);
            uint4 v = make_uint4(f2tf(g.x), f2tf(g.y), f2tf(g.z), f2tf(g.w));
            *(uint4*)(As + k * LDAB + m4 * 4) = v;
        }
        // B tile: Bs[k][n] = W[d0+n][c0+k], contiguous float4 in c
        {
            const float4 g = *(const float4*)(W + (size_t)(d0 + bn) * DD + c0 + bk4);
            Bs[(bk4 + 0) * LDAB + bn] = f2tf(g.x);
            Bs[(bk4 + 1) * LDAB + bn] = f2tf(g.y);
            Bs[(bk4 + 2) * LDAB + bn] = f2tf(g.z);
            Bs[(bk4 + 3) * LDAB + bn] = f2tf(g.w);
        }
        __syncthreads();

#pragma unroll
        for (int ks = 0; ks < 16; ks += 8) {
            uint32_t a[2][4];
#pragma unroll
            for (int mt = 0; mt < 2; mt++) {
                int mb = warp_m * 32 + mt * 16;
                a[mt][0] = As[(ks + tig) * LDAB + mb + gr];
                a[mt][1] = As[(ks + tig) * LDAB + mb + 8 + gr];
                a[mt][2] = As[(ks + 4 + tig) * LDAB + mb + gr];
                a[mt][3] = As[(ks + 4 + tig) * LDAB + mb + 8 + gr];
            }
#pragma unroll
            for (int nt = 0; nt < 4; nt++) {
                int nn = warp_n * 32 + nt * 8 + gr;
                uint32_t b0 = Bs[(ks + tig) * LDAB + nn];
                uint32_t b1 = Bs[(ks + 4 + tig) * LDAB + nn];
                MMA_TF32(acc[0][nt], a[0][0], a[0][1], a[0][2], a[0][3], b0, b1);
                MMA_TF32(acc[1][nt], a[1][0], a[1][1], a[1][2], a[1][3], b0, b1);
            }
        }
        __syncthreads();
    }

    // epilogue: C rows = t, cols = d (pairs); write head-major fp32
    float* dst;
    if (MODE == 0) {
        const int h = d0 >> 6;
        dst = g_Qh + (size_t)(nb * NH + h) * TQ * DH;
    } else {
        const int h = d0 >> 7;
        const bool isV = (d0 & 64) != 0;
        dst = (isV ? g_Vh : g_Kh) + (size_t)(nb * NH + h) * TKK * DH;
    }
#pragma unroll
    for (int nt = 0; nt < 4; nt++) {
        int col = warp_n * 32 + nt * 8 + 2 * tig;   // 0..63 within tile (=e)
        float2 bv = *(const float2*)(bias + d0 + col);
#pragma unroll
        for (int mt = 0; mt < 2; mt++) {
            int row = t0 + warp_m * 32 + mt * 16 + gr;
            float2 v0 = make_float2(acc[mt][nt][0] + bv.x, acc[mt][nt][1] + bv.y);
            float2 v1 = make_float2(acc[mt][nt][2] + bv.x, acc[mt][nt][3] + bv.y);
            *(float2*)(dst + (size_t)row * DH + col) = v0;
            *(float2*)(dst + (size_t)(row + 8) * DH + col) = v1;
        }
    }
}

// =========================================================================
// FC GEMM: out[o, t] = sum_c attO[t, c] * Wfc[o, c] + bfc[o]  (M = o, N = t)
// Same tiling as projection.
// =========================================================================
__global__ __launch_bounds__(256) void fc_mma_kernel(
    const float* __restrict__ W, const float* __restrict__ bias,
    float* __restrict__ out) {
    __shared__ uint32_t As[16 * LDAB];   // [k][m=o]
    __shared__ uint32_t Bs[16 * LDAB];   // [k][n=t]

    const int nb = blockIdx.z;
    const int o0 = blockIdx.x * 128;
    const int t0 = blockIdx.y * 64;
    const float* A = g_attO + (size_t)nb * TQ * DD;

    const int tid = threadIdx.x;
    const int wid = tid >> 5, lane = tid & 31;
    const int gr = lane >> 2, tig = lane & 3;
    const int warp_m = wid >> 1, warp_n = wid & 1;

    float acc[2][4][4];
#pragma unroll
    for (int mt = 0; mt < 2; mt++)
#pragma unroll
        for (int nt = 0; nt < 4; nt++)
#pragma unroll
            for (int i = 0; i < 4; i++) acc[mt][nt][i] = 0.f;

    const int bn = tid >> 2;
    const int bk4 = (tid & 3) * 4;

    for (int c0 = 0; c0 < DD; c0 += 16) {
        // A: As[k][m] = W[o0+m][c0+k], contiguous in c
#pragma unroll
        for (int u = 0; u < 2; u++) {
            int lin = tid + u * 256;
            int m = lin >> 2, k4 = (lin & 3) * 4;
            const float4 g = *(const float4*)(W + (size_t)(o0 + m) * DD + c0 + k4);
            As[(k4 + 0) * LDAB + m] = f2tf(g.x);
            As[(k4 + 1) * LDAB + m] = f2tf(g.y);
            As[(k4 + 2) * LDAB + m] = f2tf(g.z);
            As[(k4 + 3) * LDAB + m] = f2tf(g.w);
        }
        // B: Bs[k][n] = attO[t0+n][c0+k], contiguous in c
        {
            const float4 g = *(const float4*)(A + (size_t)(t0 + bn) * DD + c0 + bk4);
            Bs[(bk4 + 0) * LDAB + bn] = f2tf(g.x);
            Bs[(bk4 + 1) * LDAB + bn] = f2tf(g.y);
            Bs[(bk4 + 2) * LDAB + bn] = f2tf(g.z);
            Bs[(bk4 + 3) * LDAB + bn] = f2tf(g.w);
        }
        __syncthreads();

#pragma unroll
        for (int ks = 0; ks < 16; ks += 8) {
            uint32_t a[2][4];
#pragma unroll
            for (int mt = 0; mt < 2; mt++) {
                int mb = warp_m * 32 + mt * 16;
                a[mt][0] = As[(ks + tig) * LDAB + mb + gr];
                a[mt][1] = As[(ks + tig) * LDAB + mb + 8 + gr];
                a[mt][2] = As[(ks + 4 + tig) * LDAB + mb + gr];
                a[mt][3] = As[(ks + 4 + tig) * LDAB + mb + 8 + gr];
            }
#pragma unroll
            for (int nt = 0; nt < 4; nt++) {
                int nn = warp_n * 32 + nt * 8 + gr;
                uint32_t b0 = Bs[(ks + tig) * LDAB + nn];
                uint32_t b1 = Bs[(ks + 4 + tig) * LDAB + nn];
                MMA_TF32(acc[0][nt], a[0][0], a[0][1], a[0][2], a[0][3], b0, b1);
                MMA_TF32(acc[1][nt], a[1][0], a[1][1], a[1][2], a[1][3], b0, b1);
            }
        }
        __syncthreads();
    }

    // epilogue: rows = o, col pairs = consecutive t -> coalesced float2
#pragma unroll
    for (int mt = 0; mt < 2; mt++) {
        int row = o0 + warp_m * 32 + mt * 16 + gr;
        float bia0 = bias[row];
        float bia8 = bias[row + 8];
#pragma unroll
        for (int nt = 0; nt < 4; nt++) {
            int col = t0 + warp_n * 32 + nt * 8 + 2 * tig;
            float2 v0 = make_float2(acc[mt][nt][0] + bia0, acc[mt][nt][1] + bia0);
            float2 v1 = make_float2(acc[mt][nt][2] + bia8, acc[mt][nt][3] + bia8);
            *(float2*)(out + ((size_t)nb * DD + row) * TQ + col) = v0;
            *(float2*)(out + ((size_t)nb * DD + row + 8) * TQ + col) = v1;
        }
    }
}

// =========================================================================
// Flash attention, TF32 tensor cores. Block = 64 q-rows of one (n,h).
// 128 threads = 4 warps; warp handles 16 q-rows x full 64-wide k/e tiles.
// dyn smem: Qs 64x68 | Ks 64x68 | Vs 64x72 | Ss 64x68  (u32 words)
// =========================================================================
#define LQ 68
#define LK 68
#define LV 72
#define LS 68
#define ATTN_SMEM ((64 * LQ + 64 * LK + 64 * LV + 64 * LS) * 4)

__global__ __launch_bounds__(128) void attn_mma_kernel(const int* __restrict__ kv_len) {
    extern __shared__ uint32_t sm[];
    uint32_t* Qs = sm;                     // [t][e]  A-operand (m,k)
    uint32_t* Ks = Qs + 64 * LQ;           // [j][e]  B-operand for S: (n=j, k=e)
    uint32_t* Vs = Ks + 64 * LK;           // [j][e]  B-operand for O: (k=j, n=e)
    uint32_t* Ss = Vs + 64 * LV;           // [t][j]  A-operand for O

    const int bh = blockIdx.y;             // n*16 + h
    const int nb = bh >> 4;
    const int t0 = blockIdx.x * 64;
    const int len = kv_len[nb];

    const float* Qg = g_Qh + ((size_t)bh * TQ + t0) * DH;
    const float* Kg = g_Kh + (size_t)bh * TKK * DH;
    const float* Vg = g_Vh + (size_t)bh * TKK * DH;

    const int tid = threadIdx.x;
    const int w = tid >> 5, lane = tid & 31;
    const int gr = lane >> 2, tig = lane & 3;

    // load Q tile once (tf32)
#pragma unroll
    for (int u = 0; u < 8; u++) {
        int lin = tid + u * 128;
        int t = lin >> 4, e4 = lin & 15;
        const float4 g = *(const float4*)(Qg + (size_t)t * DH + e4 * 4);
        uint4 v = make_uint4(f2tf(g.x), f2tf(g.y), f2tf(g.z), f2tf(g.w));
        *(uint4*)(Qs + t * LQ + e4 * 4) = v;
    }

    float m[2], l[2], oacc[8][4];
    m[0] = m[1] = -1e30f;
    l[0] = l[1] = 0.f;
#pragma unroll
    for (int nt = 0; nt < 8; nt++)
#pragma unroll
        for (int i = 0; i < 4; i++) oacc[nt][i] = 0.f;

    const int ktiles = (len + 63) >> 6;
    for (int kt = 0; kt < ktiles; kt++) {
        const int k0 = kt * 64;
        __syncthreads();   // prior iteration's mma reads done (covers Q on iter 0)
        // load K, V tiles
#pragma unroll
        for (int u = 0; u < 8; u++) {
            int lin = tid + u * 128;
            int j = lin >> 4, e4 = lin & 15;
            const float4 gk = *(const float4*)(Kg + (size_t)(k0 + j) * DH + e4 * 4);
            *(uint4*)(Ks + j * LK + e4 * 4) =
                make_uint4(f2tf(gk.x), f2tf(gk.y), f2tf(gk.z), f2tf(gk.w));
            const float4 gv = *(const float4*)(Vg + (size_t)(k0 + j) * DH + e4 * 4);
            *(uint4*)(Vs + j * LV + e4 * 4) =
                make_uint4(f2tf(gv.x), f2tf(gv.y), f2tf(gv.z), f2tf(gv.w));
        }
        __syncthreads();

        // ---- S = Q @ K^T  (warp rows: w*16 .. w*16+15) ----
        float sacc[8][4];
#pragma unroll
        for (int nt = 0; nt < 8; nt++)
#pragma unroll
            for (int i = 0; i < 4; i++) sacc[nt][i] = 0.f;

#pragma unroll
        for (int e0 = 0; e0 < 64; e0 += 8) {
            uint32_t a0 = Qs[(w * 16 + gr) * LQ + e0 + tig];
            uint32_t a1 = Qs[(w * 16 + 8 + gr) * LQ + e0 + tig];
            uint32_t a2 = Qs[(w * 16 + gr) * LQ + e0 + 4 + tig];
            uint32_t a3 = Qs[(w * 16 + 8 + gr) * LQ + e0 + 4 + tig];
#pragma unroll
            for (int nt = 0; nt < 8; nt++) {
                uint32_t b0 = Ks[(nt * 8 + gr) * LK + e0 + tig];
                uint32_t b1 = Ks[(nt * 8 + gr) * LK + e0 + 4 + tig];
                MMA_TF32(sacc[nt], a0, a1, a2, a3, b0, b1);
            }
        }

        // ---- online softmax (rows gr, gr+8 of this warp) ----
#pragma unroll
        for (int rr = 0; rr < 2; rr++) {
            float mx = -1e30f;
#pragma unroll
            for (int nt = 0; nt < 8; nt++)
#pragma unroll
                for (int cc = 0; cc < 2; cc++) {
                    float v = sacc[nt][rr * 2 + cc] * ATT_SCALE;
                    int col = k0 + nt * 8 + 2 * tig + cc;
                    v = (col < len) ? v : -1e30f;
                    sacc[nt][rr * 2 + cc] = v;
                    mx = fmaxf(mx, v);
                }
            mx = fmaxf(mx, __shfl_xor_sync(0xffffffffu, mx, 1));
            mx = fmaxf(mx, __shfl_xor_sync(0xffffffffu, mx, 2));
            float mn = fmaxf(m[rr], mx);
            float sf = __expf(m[rr] - mn);
            m[rr] = mn;
            float sum = 0.f;
#pragma unroll
            for (int nt = 0; nt < 8; nt++)
#pragma unroll
                for (int cc = 0; cc < 2; cc++) {
                    float p = __expf(sacc[nt][rr * 2 + cc] - mn);
                    sacc[nt][rr * 2 + cc] = p;
                    sum += p;
                }
            sum += __shfl_xor_sync(0xffffffffu, sum, 1);
            sum += __shfl_xor_sync(0xffffffffu, sum, 2);
            l[rr] = l[rr] * sf + sum;
#pragma unroll
            for (int nt = 0; nt < 8; nt++)
#pragma unroll
                for (int cc = 0; cc < 2; cc++) oacc[nt][rr * 2 + cc] *= sf;
        }

        // ---- stage P into smem as tf32 (per-warp region, no block sync) ----
#pragma unroll
        for (int nt = 0; nt < 8; nt++) {
            int col = nt * 8 + 2 * tig;
            uint2 p0 = make_uint2(f2tf(sacc[nt][0]), f2tf(sacc[nt][1]));
            uint2 p1 = make_uint2(f2tf(sacc[nt][2]), f2tf(sacc[nt][3]));
            *(uint2*)(Ss + (w * 16 + gr) * LS + col) = p0;
            *(uint2*)(Ss + (w * 16 + 8 + gr) * LS + col) = p1;
        }
        __syncwarp();

        // ---- O += P @ V ----
#pragma unroll
        for (int j0 = 0; j0 < 64; j0 += 8) {
            uint32_t a0 = Ss[(w * 16 + gr) * LS + j0 + tig];
            uint32_t a1 = Ss[(w * 16 + 8 + gr) * LS + j0 + tig];
            uint32_t a2 = Ss[(w * 16 + gr) * LS + j0 + 4 + tig];
            uint32_t a3 = Ss[(w * 16 + 8 + gr) * LS + j0 + 4 + tig];
#pragma unroll
            for (int nt = 0; nt < 8; nt++) {
                uint32_t b0 = Vs[(j0 + tig) * LV + nt * 8 + gr];
                uint32_t b1 = Vs[(j0 + 4 + tig) * LV + nt * 8 + gr];
                MMA_TF32(oacc[nt], a0, a1, a2, a3, b0, b1);
            }
        }
    }

    // ---- normalize + store fp32 to g_attO[n][t][h*64+e] ----
    const int h = bh & 15;
    float inv0 = 1.0f / l[0];
    float inv1 = 1.0f / l[1];
    float* dst = g_attO + ((size_t)nb * TQ) * DD + h * DH;
#pragma unroll
    for (int nt = 0; nt < 8; nt++) {
        int col = nt * 8 + 2 * tig;
        int r0 = t0 + w * 16 + gr;
        float2 v0 = make_float2(oacc[nt][0] * inv0, oacc[nt][1] * inv0);
        float2 v1 = make_float2(oacc[nt][2] * inv1, oacc[nt][3] * inv1);
        *(float2*)(dst + (size_t)r0 * DD + col) = v0;
        *(float2*)(dst + (size_t)(r0 + 8) * DD + col) = v1;
    }
}

// =========================================================================
extern "C" void kernel_launch(void* const* d_in, const int* in_sizes, int n_in,
                              void* d_out, int out_size) {
    const float* q   = (const float*)d_in[0];
    const float* kv  = (const float*)d_in[1];
    const int*   kvl = (const int*)d_in[2];
    const float* Wq  = (const float*)d_in[3];
    const float* bq  = (const float*)d_in[4];
    const float* Wkv = (const float*)d_in[5];
    const float* bkv = (const float*)d_in[6];
    const float* Wfc = (const float*)d_in[7];
    const float* bfc = (const float*)d_in[8];
    float* out = (float*)d_out;

    cudaFuncSetAttribute(attn_mma_kernel,
                         cudaFuncAttributeMaxDynamicSharedMemorySize, ATTN_SMEM);

    // proj_q: grid (t tiles, d tiles, n)
    proj_mma_kernel<TQ, 0><<<dim3(TQ / 128, 16, NB), 256>>>(q, Wq, bq);
    // proj_kv: d spans 2048
    proj_mma_kernel<TKK, 1><<<dim3(TKK / 128, 32, NB), 256>>>(kv, Wkv, bkv);
    // attention
    attn_mma_kernel<<<dim3(TQ / 64, NB * NH), 128, ATTN_SMEM>>>(kvl);
    // fc
    fc_mma_kernel<<<dim3(DD / 128, TQ / 64, NB), 256>>>(Wfc, bfc, out);
}

// round 5
// speedup vs baseline: 3.2334x; 1.2320x over previous
#include <cuda_runtime.h>
#include <cstdint>

#define NB 8
#define TQ 512
#define TKK 1024
#define NH 16
#define DH 64
#define DD 1024
#define ATT_SCALE 0.015625f   // H/D = 16/1024

// ---------------- device scratch ----------------
__device__ float g_Qh[NB * NH * TQ * DH];   // [n,h,t,e]
__device__ float g_Kh[NB * NH * TKK * DH];  // [n,h,k,e]
__device__ float g_Vh[NB * NH * TKK * DH];  // [n,h,k,e]
__device__ float g_attO[NB * TQ * DD];      // [n,t,d], d = h*64+e

__device__ __forceinline__ uint32_t f2tf(float f) {
    uint32_t u;
    asm("cvt.rna.tf32.f32 %0, %1;" : "=r"(u) : "f"(f));
    return u;
}

#define MMA_TF32(d, a0, a1, a2, a3, b0, b1)                                   \
    asm volatile(                                                             \
        "mma.sync.aligned.m16n8k8.row.col.f32.tf32.tf32.f32 "                 \
        "{%0,%1,%2,%3}, {%4,%5,%6,%7}, {%8,%9}, {%0,%1,%2,%3};\n"             \
        : "+f"(d[0]), "+f"(d[1]), "+f"(d[2]), "+f"(d[3])                      \
        : "r"(a0), "r"(a1), "r"(a2), "r"(a3), "r"(b0), "r"(b1))

// GEMM smem pitch (words): 136 % 32 == 8 -> fragment loads conflict-free
#define GP 136
#define GEMM_STAGE (32 * GP * 2)          // words per stage (A 32xGP + B 32xGP)
#define GEMM_SMEM  (GEMM_STAGE * 2 * 4)   // 2 stages, bytes (= 69632)

// =========================================================================
// Unified 128x128 GEMM, BK=32, double-buffered. 256 threads = 8 warps
// (warp_m in 0..1 owns 64 rows; warp_n in 0..3 owns 32 cols).
// MODE 0: proj Q   C[t,d]  = act[c,t]^T W[d,c]^T   -> g_Qh   (d=h*64+e)
// MODE 1: proj KV  C[t,d]                          -> g_Kh/g_Vh (d=h*128+e)
// MODE 2: FC       C[o,t]  = Wfc[o,c] attO[t,c]^T  -> out[n,o,t]
// =========================================================================
template <int MODE>
__global__ __launch_bounds__(256, 1) void gemm128(
    const float* __restrict__ Ag, const float* __restrict__ Bg,
    const float* __restrict__ bias, float* __restrict__ out) {
    extern __shared__ uint32_t sm[];
    const int nb = blockIdx.z;
    const int m0 = blockIdx.x * 128;
    const int n0 = blockIdx.y * 128;
    const int tid = threadIdx.x;
    const int lane = tid & 31;
    const int wid = tid >> 5;
    const int gr = lane >> 2, tig = lane & 3;
    const int warp_m = wid & 1, warp_n = wid >> 1;
    const int rot = lane & 3;
    const int TD = (MODE == 0) ? TQ : TKK;

    const float* Asrc = (MODE == 2) ? Ag : Ag + (size_t)nb * DD * TD;
    const float* Bsrc = (MODE == 2) ? (const float*)g_attO + (size_t)nb * TQ * DD : Bg;

    float acc[4][4][4];
#pragma unroll
    for (int mt = 0; mt < 4; mt++)
#pragma unroll
        for (int nt = 0; nt < 4; nt++)
#pragma unroll
            for (int i = 0; i < 4; i++) acc[mt][nt][i] = 0.f;

    float4 aR[4], bR[4];

    // ---- prologue load + store stage 0 ----
#pragma unroll
    for (int u = 0; u < 4; u++) {
        int lin = tid + u * 256;
        if (MODE < 2) {
            int k = lin >> 5, m4 = lin & 31;
            aR[u] = *(const float4*)(Asrc + (size_t)k * TD + m0 + m4 * 4);
        } else {
            int r = lin >> 3, k4 = (lin & 7) * 4;
            aR[u] = *(const float4*)(Asrc + (size_t)(m0 + r) * DD + k4);
        }
        int r = lin >> 3, k4 = (lin & 7) * 4;
        bR[u] = *(const float4*)(Bsrc + (size_t)(n0 + r) * DD + k4);
    }
    {
        uint32_t* As = sm;
        uint32_t* Bs = sm + 32 * GP;
#pragma unroll
        for (int u = 0; u < 4; u++) {
            int lin = tid + u * 256;
            if (MODE < 2) {
                int k = lin >> 5, m4 = lin & 31;
                *(uint4*)(As + k * GP + m4 * 4) =
                    make_uint4(f2tf(aR[u].x), f2tf(aR[u].y), f2tf(aR[u].z), f2tf(aR[u].w));
            } else {
                int r = lin >> 3, k4 = (lin & 7) * 4;
                float av[4] = {aR[u].x, aR[u].y, aR[u].z, aR[u].w};
#pragma unroll
                for (int j = 0; j < 4; j++) {
                    int jj = (j + rot) & 3;
                    As[(k4 + jj) * GP + r] = f2tf(av[jj]);
                }
            }
            int r = lin >> 3, k4 = (lin & 7) * 4;
            float bv[4] = {bR[u].x, bR[u].y, bR[u].z, bR[u].w};
#pragma unroll
            for (int j = 0; j < 4; j++) {
                int jj = (j + rot) & 3;
                Bs[(k4 + jj) * GP + r] = f2tf(bv[jj]);
            }
        }
    }
    __syncthreads();

    // ---- main loop over K (DD/32 = 32 iterations) ----
    for (int kb = 0; kb < DD / 32; kb++) {
        const int cn = (kb + 1) * 32;
        if (kb + 1 < DD / 32) {
#pragma unroll
            for (int u = 0; u < 4; u++) {
                int lin = tid + u * 256;
                if (MODE < 2) {
                    int k = lin >> 5, m4 = lin & 31;
                    aR[u] = *(const float4*)(Asrc + (size_t)(cn + k) * TD + m0 + m4 * 4);
                } else {
                    int r = lin >> 3, k4 = (lin & 7) * 4;
                    aR[u] = *(const float4*)(Asrc + (size_t)(m0 + r) * DD + cn + k4);
                }
                int r = lin >> 3, k4 = (lin & 7) * 4;
                bR[u] = *(const float4*)(Bsrc + (size_t)(n0 + r) * DD + cn + k4);
            }
        }

        // compute current stage
        {
            uint32_t* As = sm + (kb & 1) * GEMM_STAGE;
            uint32_t* Bs = As + 32 * GP;
#pragma unroll
            for (int ks = 0; ks < 32; ks += 8) {
                uint32_t a[4][4];
#pragma unroll
                for (int mt = 0; mt < 4; mt++) {
                    int mb = warp_m * 64 + mt * 16;
                    a[mt][0] = As[(ks + tig) * GP + mb + gr];
                    a[mt][1] = As[(ks + tig) * GP + mb + 8 + gr];
                    a[mt][2] = As[(ks + 4 + tig) * GP + mb + gr];
                    a[mt][3] = As[(ks + 4 + tig) * GP + mb + 8 + gr];
                }
#pragma unroll
                for (int nt = 0; nt < 4; nt++) {
                    int nn = warp_n * 32 + nt * 8 + gr;
                    uint32_t b0 = Bs[(ks + tig) * GP + nn];
                    uint32_t b1 = Bs[(ks + 4 + tig) * GP + nn];
#pragma unroll
                    for (int mt = 0; mt < 4; mt++)
                        MMA_TF32(acc[mt][nt], a[mt][0], a[mt][1], a[mt][2], a[mt][3], b0, b1);
                }
            }
        }

        // store next stage
        if (kb + 1 < DD / 32) {
            uint32_t* As = sm + ((kb + 1) & 1) * GEMM_STAGE;
            uint32_t* Bs = As + 32 * GP;
#pragma unroll
            for (int u = 0; u < 4; u++) {
                int lin = tid + u * 256;
                if (MODE < 2) {
                    int k = lin >> 5, m4 = lin & 31;
                    *(uint4*)(As + k * GP + m4 * 4) =
                        make_uint4(f2tf(aR[u].x), f2tf(aR[u].y), f2tf(aR[u].z), f2tf(aR[u].w));
                } else {
                    int r = lin >> 3, k4 = (lin & 7) * 4;
                    float av[4] = {aR[u].x, aR[u].y, aR[u].z, aR[u].w};
#pragma unroll
                    for (int j = 0; j < 4; j++) {
                        int jj = (j + rot) & 3;
                        As[(k4 + jj) * GP + r] = f2tf(av[jj]);
                    }
                }
                int r = lin >> 3, k4 = (lin & 7) * 4;
                float bv[4] = {bR[u].x, bR[u].y, bR[u].z, bR[u].w};
#pragma unroll
                for (int j = 0; j < 4; j++) {
                    int jj = (j + rot) & 3;
                    Bs[(k4 + jj) * GP + r] = f2tf(bv[jj]);
                }
            }
        }
        __syncthreads();
    }

    // ---- epilogue ----
#pragma unroll
    for (int mt = 0; mt < 4; mt++) {
        int row = m0 + warp_m * 64 + mt * 16 + gr;
#pragma unroll
        for (int nt = 0; nt < 4; nt++) {
            int col = n0 + warp_n * 32 + nt * 8 + 2 * tig;
            if (MODE == 2) {
                float b0v = bias[row], b8v = bias[row + 8];
                float* o0 = out + ((size_t)nb * DD + row) * TQ + col;
                *(float2*)o0 = make_float2(acc[mt][nt][0] + b0v, acc[mt][nt][1] + b0v);
                *(float2*)(o0 + (size_t)8 * TQ) =
                    make_float2(acc[mt][nt][2] + b8v, acc[mt][nt][3] + b8v);
            } else {
                float2 bv = *(const float2*)(bias + col);
                float* base;
                if (MODE == 0) {
                    int h = col >> 6, e = col & 63;
                    base = g_Qh + ((size_t)(nb * NH + h) * TQ + row) * DH + e;
                } else {
                    int h = col >> 7, e = col & 63;
                    float* bb = (col & 64) ? g_Vh : g_Kh;
                    base = bb + ((size_t)(nb * NH + h) * TKK + row) * DH + e;
                }
                *(float2*)base = make_float2(acc[mt][nt][0] + bv.x, acc[mt][nt][1] + bv.y);
                *(float2*)(base + 8 * DH) =
                    make_float2(acc[mt][nt][2] + bv.x, acc[mt][nt][3] + bv.y);
            }
        }
    }
}

// =========================================================================
// Flash attention, TF32 MMA. Br=128 q-rows, Bc=64 k-cols, 128 threads =
// 4 warps, each warp owns 32 q-rows (mt=2 x nt=8 fragments).
// =========================================================================
#define LQ 68
#define LK 68
#define LV 72
#define LS 68
#define ATTN_SMEM ((128 * LQ + 64 * LK + 64 * LV + 128 * LS) * 4)

__global__ __launch_bounds__(128, 2) void attn128(const int* __restrict__ kv_len) {
    extern __shared__ uint32_t sm[];
    uint32_t* Qs = sm;                  // [t(128)][e]   A for S
    uint32_t* Ks = Qs + 128 * LQ;       // [j(64)][e]    B for S (col-major in j)
    uint32_t* Vs = Ks + 64 * LK;        // [j(64)][e]    B for O (k=j)
    uint32_t* Ss = Vs + 64 * LV;        // [t(128)][j]   A for O

    const int bh = blockIdx.y;
    const int nb = bh >> 4;
    const int t0 = blockIdx.x * 128;
    const int len = kv_len[nb];

    const float* Qg = g_Qh + ((size_t)bh * TQ + t0) * DH;
    const float* Kg = g_Kh + (size_t)bh * TKK * DH;
    const float* Vg = g_Vh + (size_t)bh * TKK * DH;

    const int tid = threadIdx.x;
    const int w = tid >> 5, lane = tid & 31;
    const int gr = lane >> 2, tig = lane & 3;

    // Q tile once: 128x64 -> 16 float4 per thread
#pragma unroll
    for (int u = 0; u < 16; u++) {
        int lin = tid + u * 128;
        int t = lin >> 4, e4 = lin & 15;
        const float4 g = *(const float4*)(Qg + (size_t)t * DH + e4 * 4);
        *(uint4*)(Qs + t * LQ + e4 * 4) =
            make_uint4(f2tf(g.x), f2tf(g.y), f2tf(g.z), f2tf(g.w));
    }

    float m[2][2], l[2][2], oacc[2][8][4];
#pragma unroll
    for (int mt = 0; mt < 2; mt++) {
        m[mt][0] = m[mt][1] = -1e30f;
        l[mt][0] = l[mt][1] = 0.f;
#pragma unroll
        for (int nt = 0; nt < 8; nt++)
#pragma unroll
            for (int i = 0; i < 4; i++) oacc[mt][nt][i] = 0.f;
    }

    const int ktiles = (len + 63) >> 6;
    for (int kt = 0; kt < ktiles; kt++) {
        const int k0 = kt * 64;
        __syncthreads();   // prior tile reads done (covers Q store on iter 0)
#pragma unroll
        for (int u = 0; u < 8; u++) {
            int lin = tid + u * 128;
            int j = lin >> 4, e4 = lin & 15;
            const float4 gk = *(const float4*)(Kg + (size_t)(k0 + j) * DH + e4 * 4);
            *(uint4*)(Ks + j * LK + e4 * 4) =
                make_uint4(f2tf(gk.x), f2tf(gk.y), f2tf(gk.z), f2tf(gk.w));
            const float4 gv = *(const float4*)(Vg + (size_t)(k0 + j) * DH + e4 * 4);
            *(uint4*)(Vs + j * LV + e4 * 4) =
                make_uint4(f2tf(gv.x), f2tf(gv.y), f2tf(gv.z), f2tf(gv.w));
        }
        __syncthreads();

        // ---- S = Q @ K^T ----
        float sacc[2][8][4];
#pragma unroll
        for (int mt = 0; mt < 2; mt++)
#pragma unroll
            for (int nt = 0; nt < 8; nt++)
#pragma unroll
                for (int i = 0; i < 4; i++) sacc[mt][nt][i] = 0.f;

#pragma unroll
        for (int e0 = 0; e0 < 64; e0 += 8) {
            uint32_t a[2][4];
#pragma unroll
            for (int mt = 0; mt < 2; mt++) {
                int rb = w * 32 + mt * 16;
                a[mt][0] = Qs[(rb + gr) * LQ + e0 + tig];
                a[mt][1] = Qs[(rb + 8 + gr) * LQ + e0 + tig];
                a[mt][2] = Qs[(rb + gr) * LQ + e0 + 4 + tig];
                a[mt][3] = Qs[(rb + 8 + gr) * LQ + e0 + 4 + tig];
            }
#pragma unroll
            for (int nt = 0; nt < 8; nt++) {
                uint32_t b0 = Ks[(nt * 8 + gr) * LK + e0 + tig];
                uint32_t b1 = Ks[(nt * 8 + gr) * LK + e0 + 4 + tig];
#pragma unroll
                for (int mt = 0; mt < 2; mt++)
                    MMA_TF32(sacc[mt][nt], a[mt][0], a[mt][1], a[mt][2], a[mt][3], b0, b1);
            }
        }

        // ---- online softmax ----
#pragma unroll
        for (int mt = 0; mt < 2; mt++)
#pragma unroll
            for (int rr = 0; rr < 2; rr++) {
                float mx = -1e30f;
#pragma unroll
                for (int nt = 0; nt < 8; nt++)
#pragma unroll
                    for (int cc = 0; cc < 2; cc++) {
                        float v = sacc[mt][nt][rr * 2 + cc] * ATT_SCALE;
                        int col = k0 + nt * 8 + 2 * tig + cc;
                        v = (col < len) ? v : -1e30f;
                        sacc[mt][nt][rr * 2 + cc] = v;
                        mx = fmaxf(mx, v);
                    }
                mx = fmaxf(mx, __shfl_xor_sync(0xffffffffu, mx, 1));
                mx = fmaxf(mx, __shfl_xor_sync(0xffffffffu, mx, 2));
                float mn = fmaxf(m[mt][rr], mx);
                float sf = __expf(m[mt][rr] - mn);
                m[mt][rr] = mn;
                float sum = 0.f;
#pragma unroll
                for (int nt = 0; nt < 8; nt++)
#pragma unroll
                    for (int cc = 0; cc < 2; cc++) {
                        float p = __expf(sacc[mt][nt][rr * 2 + cc] - mn);
                        sacc[mt][nt][rr * 2 + cc] = p;
                        sum += p;
                    }
                sum += __shfl_xor_sync(0xffffffffu, sum, 1);
                sum += __shfl_xor_sync(0xffffffffu, sum, 2);
                l[mt][rr] = l[mt][rr] * sf + sum;
#pragma unroll
                for (int nt = 0; nt < 8; nt++)
#pragma unroll
                    for (int cc = 0; cc < 2; cc++) oacc[mt][nt][rr * 2 + cc] *= sf;
            }

        // ---- stage P (per-warp rows; warp-sync only) ----
#pragma unroll
        for (int mt = 0; mt < 2; mt++) {
            int rb = w * 32 + mt * 16;
#pragma unroll
            for (int nt = 0; nt < 8; nt++) {
                int col = nt * 8 + 2 * tig;
                *(uint2*)(Ss + (rb + gr) * LS + col) =
                    make_uint2(f2tf(sacc[mt][nt][0]), f2tf(sacc[mt][nt][1]));
                *(uint2*)(Ss + (rb + 8 + gr) * LS + col) =
                    make_uint2(f2tf(sacc[mt][nt][2]), f2tf(sacc[mt][nt][3]));
            }
        }
        __syncwarp();

        // ---- O += P @ V ----
#pragma unroll
        for (int j0 = 0; j0 < 64; j0 += 8) {
            uint32_t a[2][4];
#pragma unroll
            for (int mt = 0; mt < 2; mt++) {
                int rb = w * 32 + mt * 16;
                a[mt][0] = Ss[(rb + gr) * LS + j0 + tig];
                a[mt][1] = Ss[(rb + 8 + gr) * LS + j0 + tig];
                a[mt][2] = Ss[(rb + gr) * LS + j0 + 4 + tig];
                a[mt][3] = Ss[(rb + 8 + gr) * LS + j0 + 4 + tig];
            }
#pragma unroll
            for (int nt = 0; nt < 8; nt++) {
                uint32_t b0 = Vs[(j0 + tig) * LV + nt * 8 + gr];
                uint32_t b1 = Vs[(j0 + 4 + tig) * LV + nt * 8 + gr];
#pragma unroll
                for (int mt = 0; mt < 2; mt++)
                    MMA_TF32(oacc[mt][nt], a[mt][0], a[mt][1], a[mt][2], a[mt][3], b0, b1);
            }
        }
    }

    // ---- normalize + store ----
    const int h = bh & 15;
#pragma unroll
    for (int mt = 0; mt < 2; mt++) {
        float inv0 = 1.0f / l[mt][0];
        float inv1 = 1.0f / l[mt][1];
        int r0 = t0 + w * 32 + mt * 16 + gr;
        float* dst = g_attO + ((size_t)nb * TQ + r0) * DD + h * DH;
#pragma unroll
        for (int nt = 0; nt < 8; nt++) {
            int col = nt * 8 + 2 * tig;
            *(float2*)(dst + col) =
                make_float2(oacc[mt][nt][0] * inv0, oacc[mt][nt][1] * inv0);
            *(float2*)(dst + (size_t)8 * DD + col) =
                make_float2(oacc[mt][nt][2] * inv1, oacc[mt][nt][3] * inv1);
        }
    }
}

// =========================================================================
extern "C" void kernel_launch(void* const* d_in, const int* in_sizes, int n_in,
                              void* d_out, int out_size) {
    const float* q   = (const float*)d_in[0];
    const float* kv  = (const float*)d_in[1];
    const int*   kvl = (const int*)d_in[2];
    const float* Wq  = (const float*)d_in[3];
    const float* bq  = (const float*)d_in[4];
    const float* Wkv = (const float*)d_in[5];
    const float* bkv = (const float*)d_in[6];
    const float* Wfc = (const float*)d_in[7];
    const float* bfc = (const float*)d_in[8];
    float* out = (float*)d_out;

    cudaFuncSetAttribute(gemm128<0>, cudaFuncAttributeMaxDynamicSharedMemorySize, GEMM_SMEM);
    cudaFuncSetAttribute(gemm128<1>, cudaFuncAttributeMaxDynamicSharedMemorySize, GEMM_SMEM);
    cudaFuncSetAttribute(gemm128<2>, cudaFuncAttributeMaxDynamicSharedMemorySize, GEMM_SMEM);
    cudaFuncSetAttribute(attn128, cudaFuncAttributeMaxDynamicSharedMemorySize, ATTN_SMEM);

    // proj_q: M=t (512), N=d (1024)
    gemm128<0><<<dim3(TQ / 128, DD / 128, NB), 256, GEMM_SMEM>>>(q, Wq, bq, nullptr);
    // proj_kv: M=t (1024), N=d (2048)
    gemm128<1><<<dim3(TKK / 128, 2 * DD / 128, NB), 256, GEMM_SMEM>>>(kv, Wkv, bkv, nullptr);
    // attention: Br=128
    attn128<<<dim3(TQ / 128, NB * NH), 128, ATTN_SMEM>>>(kvl);
    // fc: B operand is g_attO (device symbol, resolved inside the kernel)
    gemm128<2><<<dim3(DD / 128, TQ / 128, NB), 256, GEMM_SMEM>>>(Wfc, nullptr, bfc, out);
}

// round 7
// speedup vs baseline: 5.8118x; 1.7974x over previous
#include <cuda_runtime.h>
#include <cuda_fp16.h>
#include <cstdint>

#define NB 8
#define TQ 512
#define TKK 1024
#define NH 16
#define DH 64
#define DD 1024
#define ATT_SCALE 0.015625f   // H/D = 16/1024

// ---------------- device scratch (fp16) ----------------
__device__ __half g_qT[NB * TQ * DD];        // [n,t,c]
__device__ __half g_kvT[NB * TKK * DD];      // [n,t,c]
__device__ __half g_WqH[DD * DD];            // [d,c]
__device__ __half g_WkvH[2 * DD * DD];       // [d,c]
__device__ __half g_WfcH[DD * DD];           // [o,c]
__device__ __half g_QhH[NB * NH * TQ * DH];  // [n,h,t,e]
__device__ __half g_KhH[NB * NH * TKK * DH]; // [n,h,k,e]
__device__ __half g_VtH[NB * NH * DH * TKK]; // [n,h,e,k]  (transposed V)
__device__ __half g_attOH[NB * TQ * DD];     // [n,t,d], d=h*64+e

// ---------------- helpers ----------------
#define MMA_F16(d, a0, a1, a2, a3, b0, b1)                                    \
    asm volatile(                                                             \
        "mma.sync.aligned.m16n8k16.row.col.f32.f16.f16.f32 "                  \
        "{%0,%1,%2,%3}, {%4,%5,%6,%7}, {%8,%9}, {%0,%1,%2,%3};\n"             \
        : "+f"(d[0]), "+f"(d[1]), "+f"(d[2]), "+f"(d[3])                      \
        : "r"(a0), "r"(a1), "r"(a2), "r"(a3), "r"(b0), "r"(b1))

__device__ __forceinline__ void cp16(uint32_t dst, const void* src) {
    asm volatile("cp.async.cg.shared.global [%0], [%1], 16;\n" ::"r"(dst), "l"(src));
}
#define CP_COMMIT() asm volatile("cp.async.commit_group;\n" ::)
#define CP_WAIT1()  asm volatile("cp.async.wait_group 1;\n" ::)
#define CP_WAIT0()  asm volatile("cp.async.wait_group 0;\n" ::)

__device__ __forceinline__ uint32_t packh2(float lo, float hi) {
    __half2 h = __floats2half2_rn(lo, hi);
    return *reinterpret_cast<uint32_t*>(&h);
}

// =========================================================================
// transpose + convert: src [n][DD][TD] f32 -> g_qT/g_kvT [n][TD][DD] fp16
// DSTSEL 0 -> g_qT, 1 -> g_kvT
// =========================================================================
template <int TD, int DSTSEL>
__global__ __launch_bounds__(256) void transpose_h(const float* __restrict__ src) {
    __shared__ float tile[32][33];
    const int nb = blockIdx.z, c0 = blockIdx.y * 32, t0 = blockIdx.x * 32;
    const float* s = src + (size_t)nb * DD * TD;
    __half* d = (DSTSEL == 0 ? g_qT : g_kvT) + (size_t)nb * TD * DD;
    const int tx = threadIdx.x & 31, ty = threadIdx.x >> 5;
#pragma unroll
    for (int i = 0; i < 4; i++)
        tile[ty + 8 * i][tx] = s[(size_t)(c0 + ty + 8 * i) * TD + t0 + tx];
    __syncthreads();
#pragma unroll
    for (int i = 0; i < 4; i++)
        d[(size_t)(t0 + ty + 8 * i) * DD + c0 + tx] =
            __float2half_rn(tile[tx][ty + 8 * i]);
}

// fp32 -> fp16 weight convert. WSEL 0: Wq, 1: Wkv, 2: Wfc (n4 = elems/4)
template <int WSEL>
__global__ void convert_h(const float* __restrict__ s, int n4) {
    __half* d = (WSEL == 0) ? g_WqH : (WSEL == 1) ? g_WkvH : g_WfcH;
    int i = blockIdx.x * blockDim.x + threadIdx.x;
    if (i < n4) {
        float4 v = ((const float4*)s)[i];
        __half2* dd = (__half2*)d + i * 2;
        dd[0] = __floats2half2_rn(v.x, v.y);
        dd[1] = __floats2half2_rn(v.z, v.w);
    }
}

// =========================================================================
// fp16 GEMM 128x128, BK=32, cp.async 3-stage. 256 thr = 8 warps (2m x 4n),
// warp tile 64x32. All operands fp16 row-major K-contiguous (stride DD).
// MODE 0: Q proj   A=g_qT[n] (t x c), B=g_WqH  -> g_QhH
// MODE 1: KV proj  A=g_kvT[n],        B=g_WkvH -> g_KhH / g_VtH (transposed)
// MODE 2: FC       A=g_WfcH (o x c),  B=g_attOH[n] -> out[n,o,t] fp32
// =========================================================================
#define HP 20                      // smem row pitch in 32-bit words (40 fp16)
#define HTILE_W (128 * HP)         // words per tile (2560)
#define HSTG_W (2 * HTILE_W)       // words per stage (A+B)
#define HGEMM_SMEM (3 * HSTG_W * 4)  // bytes = 61440

template <int MODE>
__global__ __launch_bounds__(256, 2) void hgemm(
    const float* __restrict__ bias, float* __restrict__ out) {
    extern __shared__ uint32_t sw[];
    const uint32_t sbase = (uint32_t)__cvta_generic_to_shared(sw);

    const int nb = blockIdx.z;
    const int m0 = blockIdx.x * 128;
    const int n0 = blockIdx.y * 128;
    const int tid = threadIdx.x;
    const int lane = tid & 31, wid = tid >> 5;
    const int gr = lane >> 2, tig = lane & 3;
    const int warp_m = wid & 1, warp_n = wid >> 1;

    const __half* Asrc = (MODE == 0) ? g_qT + (size_t)nb * TQ * DD
                       : (MODE == 1) ? g_kvT + (size_t)nb * TKK * DD
                                     : g_WfcH;
    const __half* Bsrc = (MODE == 0) ? g_WqH
                       : (MODE == 1) ? g_WkvH
                                     : g_attOH + (size_t)nb * TQ * DD;

    float acc[4][4][4];
#pragma unroll
    for (int mt = 0; mt < 4; mt++)
#pragma unroll
        for (int nt = 0; nt < 4; nt++)
#pragma unroll
            for (int i = 0; i < 4; i++) acc[mt][nt][i] = 0.f;

    // per-thread cp.async assignment: 2 A-chunks + 2 B-chunks (16B each)
    const int ca0 = tid * 2;

    auto issue = [&](int s, int kb) {
        const uint32_t stA = sbase + s * (HSTG_W * 4);
        const uint32_t stB = stA + HTILE_W * 4;
#pragma unroll
        for (int u = 0; u < 2; u++) {
            int ca = ca0 + u;
            int r = ca >> 2, ch = ca & 3;
            cp16(stA + (r * HP + ch * 4) * 4,
                 Asrc + (size_t)(m0 + r) * DD + kb * 32 + ch * 8);
            cp16(stB + (r * HP + ch * 4) * 4,
                 Bsrc + (size_t)(n0 + r) * DD + kb * 32 + ch * 8);
        }
    };

    issue(0, 0); CP_COMMIT();
    issue(1, 1); CP_COMMIT();

    const int KB = DD / 32;   // 32
    for (int kb = 0; kb < KB; kb++) {
        if (kb == KB - 1) { CP_WAIT0(); } else { CP_WAIT1(); }
        __syncthreads();
        if (kb + 2 < KB) { issue((kb + 2) % 3, kb + 2); CP_COMMIT(); }

        const uint32_t* As = sw + (kb % 3) * HSTG_W;
        const uint32_t* Bs = As + HTILE_W;
#pragma unroll
        for (int ks = 0; ks < 2; ks++) {        // two k16 steps
            const int kw = ks * 8;
            uint32_t a[4][4];
#pragma unroll
            for (int mt = 0; mt < 4; mt++) {
                int mb = warp_m * 64 + mt * 16;
                a[mt][0] = As[(mb + gr) * HP + kw + tig];
                a[mt][1] = As[(mb + 8 + gr) * HP + kw + tig];
                a[mt][2] = As[(mb + gr) * HP + kw + 4 + tig];
                a[mt][3] = As[(mb + 8 + gr) * HP + kw + 4 + tig];
            }
#pragma unroll
            for (int nt = 0; nt < 4; nt++) {
                int nn = warp_n * 32 + nt * 8 + gr;
                uint32_t b0 = Bs[nn * HP + kw + tig];
                uint32_t b1 = Bs[nn * HP + kw + 4 + tig];
#pragma unroll
                for (int mt = 0; mt < 4; mt++)
                    MMA_F16(acc[mt][nt], a[mt][0], a[mt][1], a[mt][2], a[mt][3], b0, b1);
            }
        }
    }

    // ---- epilogue ----
#pragma unroll
    for (int mt = 0; mt < 4; mt++) {
        int row = m0 + warp_m * 64 + mt * 16 + gr;
#pragma unroll
        for (int nt = 0; nt < 4; nt++) {
            int col = n0 + warp_n * 32 + nt * 8 + 2 * tig;
            if (MODE == 2) {
                float b0v = bias[row], b8v = bias[row + 8];
                float* o0 = out + ((size_t)nb * DD + row) * TQ + col;
                *(float2*)o0 = make_float2(acc[mt][nt][0] + b0v, acc[mt][nt][1] + b0v);
                *(float2*)(o0 + (size_t)8 * TQ) =
                    make_float2(acc[mt][nt][2] + b8v, acc[mt][nt][3] + b8v);
            } else {
                float2 bv = *(const float2*)(bias + col);
                float v0 = acc[mt][nt][0] + bv.x, v1 = acc[mt][nt][1] + bv.y;
                float v2 = acc[mt][nt][2] + bv.x, v3 = acc[mt][nt][3] + bv.y;
                if (MODE == 0) {
                    int h = col >> 6, e = col & 63;
                    __half* dst = g_QhH + ((size_t)(nb * NH + h) * TQ + row) * DH + e;
                    *(__half2*)dst = __floats2half2_rn(v0, v1);
                    *(__half2*)(dst + 8 * DH) = __floats2half2_rn(v2, v3);
                } else {
                    int h = col >> 7, e = col & 127;
                    if (e < 64) {
                        __half* dst = g_KhH + ((size_t)(nb * NH + h) * TKK + row) * DH + e;
                        *(__half2*)dst = __floats2half2_rn(v0, v1);
                        *(__half2*)(dst + 8 * DH) = __floats2half2_rn(v2, v3);
                    } else {
                        int ee = e - 64;
                        __half* hb = g_VtH + ((size_t)(nb * NH + h) * DH + ee) * TKK;
                        hb[row] = __float2half_rn(v0);
                        hb[TKK + row] = __float2half_rn(v1);
                        hb[row + 8] = __float2half_rn(v2);
                        hb[TKK + row + 8] = __float2half_rn(v3);
                    }
                }
            }
        }
    }
}

// =========================================================================
// fp16 flash attention. Br=128 q-rows, Bc=64, 4 warps x 32 rows.
// P passes through registers (S C-frag == PV A-frag). V pre-transposed.
// =========================================================================
#define AP 36                      // smem pitch (words) for 64-fp16 rows
#define ATTN_SMEM ((128 * AP + 64 * AP + 64 * AP) * 4)   // 36864 B

__global__ __launch_bounds__(128, 2) void attn_h(const int* __restrict__ kv_len) {
    extern __shared__ uint32_t sw[];
    uint32_t* Qs = sw;               // [t(128)][e]
    uint32_t* Ks = Qs + 128 * AP;    // [j(64)][e]
    uint32_t* Vs = Ks + 64 * AP;     // [e(64)][j]   (V^T tile)

    const int bh = blockIdx.y;
    const int nb = bh >> 4;
    const int t0 = blockIdx.x * 128;
    const int len = kv_len[nb];

    const __half* Qg = g_QhH + ((size_t)bh * TQ + t0) * DH;
    const __half* Kg = g_KhH + (size_t)bh * TKK * DH;
    const __half* Vt = g_VtH + (size_t)bh * DH * TKK;

    const int tid = threadIdx.x;
    const int w = tid >> 5, lane = tid & 31;
    const int gr = lane >> 2, tig = lane & 3;
    const int rb = w * 32;

    // Q tile once (fp16, direct copy)
#pragma unroll
    for (int u = 0; u < 8; u++) {
        int lin = tid + u * 128;
        int row = lin >> 3, ch = lin & 7;
        uint4 v = *(const uint4*)(Qg + (size_t)row * DH + ch * 8);
        *(uint4*)(Qs + row * AP + ch * 4) = v;
    }

    float m[2][2], l[2][2], oacc[2][8][4];
#pragma unroll
    for (int mt = 0; mt < 2; mt++) {
        m[mt][0] = m[mt][1] = -1e30f;
        l[mt][0] = l[mt][1] = 0.f;
#pragma unroll
        for (int nt = 0; nt < 8; nt++)
#pragma unroll
            for (int i = 0; i < 4; i++) oacc[mt][nt][i] = 0.f;
    }

    const int ktiles = (len + 63) >> 6;
    for (int kt = 0; kt < ktiles; kt++) {
        const int k0 = kt * 64;
        __syncthreads();   // prior tile mma reads done
#pragma unroll
        for (int u = 0; u < 4; u++) {
            int lin = tid + u * 128;
            int row = lin >> 3, ch = lin & 7;
            uint4 kv4 = *(const uint4*)(Kg + (size_t)(k0 + row) * DH + ch * 8);
            *(uint4*)(Ks + row * AP + ch * 4) = kv4;
            uint4 vv4 = *(const uint4*)(Vt + (size_t)row * TKK + k0 + ch * 8);
            *(uint4*)(Vs + row * AP + ch * 4) = vv4;
        }
        __syncthreads();

        // ---- S = Q @ K^T ----
        float sacc[2][8][4];
#pragma unroll
        for (int mt = 0; mt < 2; mt++)
#pragma unroll
            for (int nt = 0; nt < 8; nt++)
#pragma unroll
                for (int i = 0; i < 4; i++) sacc[mt][nt][i] = 0.f;

#pragma unroll
        for (int es = 0; es < 4; es++) {       // k16 steps over e
            const int ew = es * 8;
            uint32_t a[2][4];
#pragma unroll
            for (int mt = 0; mt < 2; mt++) {
                int r = rb + mt * 16;
                a[mt][0] = Qs[(r + gr) * AP + ew + tig];
                a[mt][1] = Qs[(r + 8 + gr) * AP + ew + tig];
                a[mt][2] = Qs[(r + gr) * AP + ew + 4 + tig];
                a[mt][3] = Qs[(r + 8 + gr) * AP + ew + 4 + tig];
            }
#pragma unroll
            for (int nt = 0; nt < 8; nt++) {
                uint32_t b0 = Ks[(nt * 8 + gr) * AP + ew + tig];
                uint32_t b1 = Ks[(nt * 8 + gr) * AP + ew + 4 + tig];
#pragma unroll
                for (int mt = 0; mt < 2; mt++)
                    MMA_F16(sacc[mt][nt], a[mt][0], a[mt][1], a[mt][2], a[mt][3], b0, b1);
            }
        }

        // ---- online softmax ----
#pragma unroll
        for (int mt = 0; mt < 2; mt++)
#pragma unroll
            for (int rr = 0; rr < 2; rr++) {
                float mx = -1e30f;
#pragma unroll
                for (int nt = 0; nt < 8; nt++)
#pragma unroll
                    for (int cc = 0; cc < 2; cc++) {
                        float v = sacc[mt][nt][rr * 2 + cc] * ATT_SCALE;
                        int col = k0 + nt * 8 + 2 * tig + cc;
                        v = (col < len) ? v : -1e30f;
                        sacc[mt][nt][rr * 2 + cc] = v;
                        mx = fmaxf(mx, v);
                    }
                mx = fmaxf(mx, __shfl_xor_sync(0xffffffffu, mx, 1));
                mx = fmaxf(mx, __shfl_xor_sync(0xffffffffu, mx, 2));
                float mn = fmaxf(m[mt][rr], mx);
                float sf = __expf(m[mt][rr] - mn);
                m[mt][rr] = mn;
                float sum = 0.f;
#pragma unroll
                for (int nt = 0; nt < 8; nt++)
#pragma unroll
                    for (int cc = 0; cc < 2; cc++) {
                        float p = __expf(sacc[mt][nt][rr * 2 + cc] - mn);
                        sacc[mt][nt][rr * 2 + cc] = p;
                        sum += p;
                    }
                sum += __shfl_xor_sync(0xffffffffu, sum, 1);
                sum += __shfl_xor_sync(0xffffffffu, sum, 2);
                l[mt][rr] = l[mt][rr] * sf + sum;
#pragma unroll
                for (int nt = 0; nt < 8; nt++)
#pragma unroll
                    for (int cc = 0; cc < 2; cc++) oacc[mt][nt][rr * 2 + cc] *= sf;
            }

        // ---- O += P @ V (P via registers) ----
#pragma unroll
        for (int js = 0; js < 4; js++) {       // k16 steps over j
            uint32_t pa[2][4];
#pragma unroll
            for (int mt = 0; mt < 2; mt++) {
                pa[mt][0] = packh2(sacc[mt][2 * js][0], sacc[mt][2 * js][1]);
                pa[mt][1] = packh2(sacc[mt][2 * js][2], sacc[mt][2 * js][3]);
                pa[mt][2] = packh2(sacc[mt][2 * js + 1][0], sacc[mt][2 * js + 1][1]);
                pa[mt][3] = packh2(sacc[mt][2 * js + 1][2], sacc[mt][2 * js + 1][3]);
            }
#pragma unroll
            for (int nt = 0; nt < 8; nt++) {
                uint32_t b0 = Vs[(nt * 8 + gr) * AP + js * 8 + tig];
                uint32_t b1 = Vs[(nt * 8 + gr) * AP + js * 8 + 4 + tig];
#pragma unroll
                for (int mt = 0; mt < 2; mt++)
                    MMA_F16(oacc[mt][nt], pa[mt][0], pa[mt][1], pa[mt][2], pa[mt][3], b0, b1);
            }
        }
    }

    // ---- normalize + store fp16 to g_attOH[n][t][h*64+e] ----
    const int h = bh & 15;
#pragma unroll
    for (int mt = 0; mt < 2; mt++) {
        float inv0 = 1.0f / l[mt][0];
        float inv1 = 1.0f / l[mt][1];
        int r0 = t0 + rb + mt * 16 + gr;
        __half* dst = g_attOH + ((size_t)nb * TQ + r0) * DD + h * DH;
#pragma unroll
        for (int nt = 0; nt < 8; nt++) {
            int col = nt * 8 + 2 * tig;
            *(__half2*)(dst + col) =
                __floats2half2_rn(oacc[mt][nt][0] * inv0, oacc[mt][nt][1] * inv0);
            *(__half2*)(dst + (size_t)8 * DD + col) =
                __floats2half2_rn(oacc[mt][nt][2] * inv1, oacc[mt][nt][3] * inv1);
        }
    }
}

// =========================================================================
extern "C" void kernel_launch(void* const* d_in, const int* in_sizes, int n_in,
                              void* d_out, int out_size) {
    const float* q   = (const float*)d_in[0];
    const float* kv  = (const float*)d_in[1];
    const int*   kvl = (const int*)d_in[2];
    const float* Wq  = (const float*)d_in[3];
    const float* bq  = (const float*)d_in[4];
    const float* Wkv = (const float*)d_in[5];
    const float* bkv = (const float*)d_in[6];
    const float* Wfc = (const float*)d_in[7];
    const float* bfc = (const float*)d_in[8];
    float* out = (float*)d_out;

    cudaFuncSetAttribute(hgemm<0>, cudaFuncAttributeMaxDynamicSharedMemorySize, HGEMM_SMEM);
    cudaFuncSetAttribute(hgemm<1>, cudaFuncAttributeMaxDynamicSharedMemorySize, HGEMM_SMEM);
    cudaFuncSetAttribute(hgemm<2>, cudaFuncAttributeMaxDynamicSharedMemorySize, HGEMM_SMEM);
    cudaFuncSetAttribute(attn_h, cudaFuncAttributeMaxDynamicSharedMemorySize, ATTN_SMEM);

    // 1. transposes + weight converts (fp32 -> fp16); destinations are
    //    __device__ globals referenced inside the kernels (no symbol API).
    transpose_h<TQ, 0><<<dim3(TQ / 32, DD / 32, NB), 256>>>(q);
    transpose_h<TKK, 1><<<dim3(TKK / 32, DD / 32, NB), 256>>>(kv);
    convert_h<0><<<(DD * DD / 4 + 255) / 256, 256>>>(Wq, DD * DD / 4);
    convert_h<1><<<(2 * DD * DD / 4 + 255) / 256, 256>>>(Wkv, 2 * DD * DD / 4);
    convert_h<2><<<(DD * DD / 4 + 255) / 256, 256>>>(Wfc, DD * DD / 4);

    // 2. projections
    hgemm<0><<<dim3(TQ / 128, DD / 128, NB), 256, HGEMM_SMEM>>>(bq, nullptr);
    hgemm<1><<<dim3(TKK / 128, 2 * DD / 128, NB), 256, HGEMM_SMEM>>>(bkv, nullptr);
    // 3. attention
    attn_h<<<dim3(TQ / 128, NB * NH), 128, ATTN_SMEM>>>(kvl);
    // 4. fc
    hgemm<2><<<dim3(DD / 128, TQ / 128, NB), 256, HGEMM_SMEM>>>(bfc, out);
}

// round 8
// speedup vs baseline: 6.4155x; 1.1039x over previous
#include <cuda_runtime.h>
#include <cuda_fp16.h>
#include <cstdint>

#define NB 8
#define TQ 512
#define TKK 1024
#define NH 16
#define DH 64
#define DD 1024
#define ATT_SCALE 0.015625f   // H/D = 16/1024

// ---------------- device scratch (fp16) ----------------
__device__ __half g_qT[NB * TQ * DD];        // [n,t,c]
__device__ __half g_kvT[NB * TKK * DD];      // [n,t,c]
__device__ __half g_WqH[DD * DD];            // [d,c]
__device__ __half g_WkvH[2 * DD * DD];       // [d,c]
__device__ __half g_WfcH[DD * DD];           // [o,c]
__device__ __half g_QhH[NB * NH * TQ * DH];  // [n,h,t,e]
__device__ __half g_KhH[NB * NH * TKK * DH]; // [n,h,k,e]
__device__ __half g_VtH[NB * NH * DH * TKK]; // [n,h,e,k]  (transposed V)
__device__ __half g_attOH[NB * TQ * DD];     // [n,t,d], d=h*64+e

// ---------------- helpers ----------------
#define MMA_F16(d, a0, a1, a2, a3, b0, b1)                                    \
    asm volatile(                                                             \
        "mma.sync.aligned.m16n8k16.row.col.f32.f16.f16.f32 "                  \
        "{%0,%1,%2,%3}, {%4,%5,%6,%7}, {%8,%9}, {%0,%1,%2,%3};\n"             \
        : "+f"(d[0]), "+f"(d[1]), "+f"(d[2]), "+f"(d[3])                      \
        : "r"(a0), "r"(a1), "r"(a2), "r"(a3), "r"(b0), "r"(b1))

__device__ __forceinline__ void ldsm_x4(uint32_t& r0, uint32_t& r1,
                                        uint32_t& r2, uint32_t& r3,
                                        uint32_t addr) {
    asm volatile("ldmatrix.sync.aligned.m8n8.x4.shared.b16 {%0,%1,%2,%3}, [%4];"
                 : "=r"(r0), "=r"(r1), "=r"(r2), "=r"(r3) : "r"(addr));
}

__device__ __forceinline__ void cp16(uint32_t dst, const void* src) {
    asm volatile("cp.async.cg.shared.global [%0], [%1], 16;\n" ::"r"(dst), "l"(src));
}
#define CP_COMMIT() asm volatile("cp.async.commit_group;\n" ::)
#define CP_WAIT1()  asm volatile("cp.async.wait_group 1;\n" ::)
#define CP_WAIT0()  asm volatile("cp.async.wait_group 0;\n" ::)

__device__ __forceinline__ uint32_t packh2(float lo, float hi) {
    __half2 h = __floats2half2_rn(lo, hi);
    return *reinterpret_cast<uint32_t*>(&h);
}

// =========================================================================
// transpose + convert: src [n][DD][TD] f32 -> g_qT/g_kvT [n][TD][DD] fp16
// =========================================================================
template <int TD, int DSTSEL>
__global__ __launch_bounds__(256) void transpose_h(const float* __restrict__ src) {
    __shared__ float tile[32][33];
    const int nb = blockIdx.z, c0 = blockIdx.y * 32, t0 = blockIdx.x * 32;
    const float* s = src + (size_t)nb * DD * TD;
    __half* d = (DSTSEL == 0 ? g_qT : g_kvT) + (size_t)nb * TD * DD;
    const int tx = threadIdx.x & 31, ty = threadIdx.x >> 5;
#pragma unroll
    for (int i = 0; i < 4; i++)
        tile[ty + 8 * i][tx] = s[(size_t)(c0 + ty + 8 * i) * TD + t0 + tx];
    __syncthreads();
#pragma unroll
    for (int i = 0; i < 4; i++)
        d[(size_t)(t0 + ty + 8 * i) * DD + c0 + tx] =
            __float2half_rn(tile[tx][ty + 8 * i]);
}

// fp32 -> fp16 weight convert. WSEL 0: Wq, 1: Wkv, 2: Wfc (n4 = elems/4)
template <int WSEL>
__global__ void convert_h(const float* __restrict__ s, int n4) {
    __half* d = (WSEL == 0) ? g_WqH : (WSEL == 1) ? g_WkvH : g_WfcH;
    int i = blockIdx.x * blockDim.x + threadIdx.x;
    if (i < n4) {
        float4 v = ((const float4*)s)[i];
        __half2* dd = (__half2*)d + i * 2;
        dd[0] = __floats2half2_rn(v.x, v.y);
        dd[1] = __floats2half2_rn(v.z, v.w);
    }
}

// =========================================================================
// fp16 GEMM 128x128, BK=32, cp.async 3-stage, ldmatrix fragment loads.
// 256 thr = 8 warps (2m x 4n), warp tile 64x32.
// MODE 0: Q proj -> g_QhH.  MODE 1: KV proj -> g_KhH/g_VtH.  MODE 2: FC.
// =========================================================================
#define HP 20                      // smem row pitch in 32-bit words (40 fp16)
#define HTILE_W (128 * HP)
#define HSTG_W (2 * HTILE_W)
#define HGEMM_SMEM (3 * HSTG_W * 4)  // 61440 B

template <int MODE>
__global__ __launch_bounds__(256, 2) void hgemm(
    const float* __restrict__ bias, float* __restrict__ out) {
    extern __shared__ uint32_t sw[];
    const uint32_t sbase = (uint32_t)__cvta_generic_to_shared(sw);

    const int nb = blockIdx.z;
    const int m0 = blockIdx.x * 128;
    const int n0 = blockIdx.y * 128;
    const int tid = threadIdx.x;
    const int lane = tid & 31, wid = tid >> 5;
    const int gr = lane >> 2, tig = lane & 3;
    const int warp_m = wid & 1, warp_n = wid >> 1;

    // ldmatrix lane offsets (bytes)
    const uint32_t aOff = ((lane & 15) * HP + ((lane >> 4) & 1) * 4) * 4;
    const uint32_t bOff =
        (((lane & 7) + ((lane >> 4) & 1) * 8) * HP + ((lane >> 3) & 1) * 4) * 4;

    const __half* Asrc = (MODE == 0) ? g_qT + (size_t)nb * TQ * DD
                       : (MODE == 1) ? g_kvT + (size_t)nb * TKK * DD
                                     : g_WfcH;
    const __half* Bsrc = (MODE == 0) ? g_WqH
                       : (MODE == 1) ? g_WkvH
                                     : g_attOH + (size_t)nb * TQ * DD;

    float acc[4][4][4];
#pragma unroll
    for (int mt = 0; mt < 4; mt++)
#pragma unroll
        for (int nt = 0; nt < 4; nt++)
#pragma unroll
            for (int i = 0; i < 4; i++) acc[mt][nt][i] = 0.f;

    const int ca0 = tid * 2;
    auto issue = [&](int s, int kb) {
        const uint32_t stA = sbase + s * (HSTG_W * 4);
        const uint32_t stB = stA + HTILE_W * 4;
#pragma unroll
        for (int u = 0; u < 2; u++) {
            int ca = ca0 + u;
            int r = ca >> 2, ch = ca & 3;
            cp16(stA + (r * HP + ch * 4) * 4,
                 Asrc + (size_t)(m0 + r) * DD + kb * 32 + ch * 8);
            cp16(stB + (r * HP + ch * 4) * 4,
                 Bsrc + (size_t)(n0 + r) * DD + kb * 32 + ch * 8);
        }
    };

    issue(0, 0); CP_COMMIT();
    issue(1, 1); CP_COMMIT();

    const int KB = DD / 32;   // 32
    for (int kb = 0; kb < KB; kb++) {
        if (kb == KB - 1) { CP_WAIT0(); } else { CP_WAIT1(); }
        __syncthreads();
        if (kb + 2 < KB) { issue((kb + 2) % 3, kb + 2); CP_COMMIT(); }

        const uint32_t stA = sbase + (kb % 3) * (HSTG_W * 4);
        const uint32_t stB = stA + HTILE_W * 4;
#pragma unroll
        for (int ks = 0; ks < 2; ks++) {        // two k16 steps
            const int kw = ks * 8;
            uint32_t a[4][4];
#pragma unroll
            for (int mt = 0; mt < 4; mt++)
                ldsm_x4(a[mt][0], a[mt][1], a[mt][2], a[mt][3],
                        stA + ((warp_m * 64 + mt * 16) * HP + kw) * 4 + aOff);
            uint32_t b[4][2];
#pragma unroll
            for (int np = 0; np < 2; np++)
                ldsm_x4(b[2 * np][0], b[2 * np][1], b[2 * np + 1][0], b[2 * np + 1][1],
                        stB + ((warp_n * 32 + np * 16) * HP + kw) * 4 + bOff);
#pragma unroll
            for (int nt = 0; nt < 4; nt++)
#pragma unroll
                for (int mt = 0; mt < 4; mt++)
                    MMA_F16(acc[mt][nt], a[mt][0], a[mt][1], a[mt][2], a[mt][3],
                            b[nt][0], b[nt][1]);
        }
    }

    // ---- epilogue ----
#pragma unroll
    for (int mt = 0; mt < 4; mt++) {
        int row = m0 + warp_m * 64 + mt * 16 + gr;
#pragma unroll
        for (int nt = 0; nt < 4; nt++) {
            int col = n0 + warp_n * 32 + nt * 8 + 2 * tig;
            if (MODE == 2) {
                float b0v = bias[row], b8v = bias[row + 8];
                float* o0 = out + ((size_t)nb * DD + row) * TQ + col;
                *(float2*)o0 = make_float2(acc[mt][nt][0] + b0v, acc[mt][nt][1] + b0v);
                *(float2*)(o0 + (size_t)8 * TQ) =
                    make_float2(acc[mt][nt][2] + b8v, acc[mt][nt][3] + b8v);
            } else {
                float2 bv = *(const float2*)(bias + col);
                float v0 = acc[mt][nt][0] + bv.x, v1 = acc[mt][nt][1] + bv.y;
                float v2 = acc[mt][nt][2] + bv.x, v3 = acc[mt][nt][3] + bv.y;
                if (MODE == 0) {
                    int h = col >> 6, e = col & 63;
                    __half* dst = g_QhH + ((size_t)(nb * NH + h) * TQ + row) * DH + e;
                    *(__half2*)dst = __floats2half2_rn(v0, v1);
                    *(__half2*)(dst + 8 * DH) = __floats2half2_rn(v2, v3);
                } else {
                    int h = col >> 7, e = col & 127;
                    if (e < 64) {
                        __half* dst = g_KhH + ((size_t)(nb * NH + h) * TKK + row) * DH + e;
                        *(__half2*)dst = __floats2half2_rn(v0, v1);
                        *(__half2*)(dst + 8 * DH) = __floats2half2_rn(v2, v3);
                    } else {
                        int ee = e - 64;
                        __half* hb = g_VtH + ((size_t)(nb * NH + h) * DH + ee) * TKK;
                        hb[row] = __float2half_rn(v0);
                        hb[TKK + row] = __float2half_rn(v1);
                        hb[row + 8] = __float2half_rn(v2);
                        hb[TKK + row + 8] = __float2half_rn(v3);
                    }
                }
            }
        }
    }
}

// =========================================================================
// fp16 flash attention. Br=128, Bc=64, 4 warps x 32 rows. ldmatrix loads,
// cp.async double-buffered K/V tiles, register P-passing, transposed V.
// smem: Qs 128xAP | stage0 {Ks,Vs} | stage1 {Ks,Vs}  (64xAP each)
// =========================================================================
#define AP 36
#define KV_STG_W (128 * AP)                        // words per stage (K+V)
#define ATTN_SMEM ((128 * AP + 2 * KV_STG_W) * 4)  // 55296 B

__global__ __launch_bounds__(128, 2) void attn_h(const int* __restrict__ kv_len) {
    extern __shared__ uint32_t sw[];
    const uint32_t sbase = (uint32_t)__cvta_generic_to_shared(sw);
    uint32_t* Qs = sw;               // [t(128)][e]

    const int bh = blockIdx.y;
    const int nb = bh >> 4;
    const int t0 = blockIdx.x * 128;
    const int len = kv_len[nb];

    const __half* Qg = g_QhH + ((size_t)bh * TQ + t0) * DH;
    const __half* Kg = g_KhH + (size_t)bh * TKK * DH;
    const __half* Vt = g_VtH + (size_t)bh * DH * TKK;

    const int tid = threadIdx.x;
    const int w = tid >> 5, lane = tid & 31;
    const int gr = lane >> 2, tig = lane & 3;
    const int rb = w * 32;

    const uint32_t aOff = ((lane & 15) * AP + ((lane >> 4) & 1) * 4) * 4;
    const uint32_t bOff =
        (((lane & 7) + ((lane >> 4) & 1) * 8) * AP + ((lane >> 3) & 1) * 4) * 4;

    // Q tile once
#pragma unroll
    for (int u = 0; u < 8; u++) {
        int lin = tid + u * 128;
        int row = lin >> 3, ch = lin & 7;
        uint4 v = *(const uint4*)(Qg + (size_t)row * DH + ch * 8);
        *(uint4*)(Qs + row * AP + ch * 4) = v;
    }

    auto issueKV = [&](int kt, int s) {
        const uint32_t stK = sbase + (128 * AP + s * KV_STG_W) * 4;
        const uint32_t stV = stK + 64 * AP * 4;
        const int k0 = kt * 64;
#pragma unroll
        for (int u = 0; u < 4; u++) {
            int lin = tid + u * 128;
            int row = lin >> 3, ch = lin & 7;
            cp16(stK + (row * AP + ch * 4) * 4,
                 Kg + (size_t)(k0 + row) * DH + ch * 8);
            cp16(stV + (row * AP + ch * 4) * 4,
                 Vt + (size_t)row * TKK + k0 + ch * 8);
        }
    };

    float m[2][2], l[2][2], oacc[2][8][4];
#pragma unroll
    for (int mt = 0; mt < 2; mt++) {
        m[mt][0] = m[mt][1] = -1e30f;
        l[mt][0] = l[mt][1] = 0.f;
#pragma unroll
        for (int nt = 0; nt < 8; nt++)
#pragma unroll
            for (int i = 0; i < 4; i++) oacc[mt][nt][i] = 0.f;
    }

    const int ktiles = (len + 63) >> 6;
    issueKV(0, 0); CP_COMMIT();

    for (int kt = 0; kt < ktiles; kt++) {
        const int k0 = kt * 64;
        const int st = kt & 1;
        __syncthreads();   // prior compute reads done (also covers Q stores)
        if (kt + 1 < ktiles) { issueKV(kt + 1, st ^ 1); CP_COMMIT(); CP_WAIT1(); }
        else                 { CP_WAIT0(); }
        __syncthreads();

        const uint32_t stK = sbase + (128 * AP + st * KV_STG_W) * 4;
        const uint32_t stV = stK + 64 * AP * 4;

        // ---- S = Q @ K^T ----
        float sacc[2][8][4];
#pragma unroll
        for (int mt = 0; mt < 2; mt++)
#pragma unroll
            for (int nt = 0; nt < 8; nt++)
#pragma unroll
                for (int i = 0; i < 4; i++) sacc[mt][nt][i] = 0.f;

#pragma unroll
        for (int es = 0; es < 4; es++) {
            const int ew = es * 8;
            uint32_t a[2][4];
#pragma unroll
            for (int mt = 0; mt < 2; mt++)
                ldsm_x4(a[mt][0], a[mt][1], a[mt][2], a[mt][3],
                        sbase + ((rb + mt * 16) * AP + ew) * 4 + aOff);
            uint32_t b[8][2];
#pragma unroll
            for (int np = 0; np < 4; np++)
                ldsm_x4(b[2 * np][0], b[2 * np][1], b[2 * np + 1][0], b[2 * np + 1][1],
                        stK + (np * 16 * AP + ew) * 4 + bOff);
#pragma unroll
            for (int nt = 0; nt < 8; nt++)
#pragma unroll
                for (int mt = 0; mt < 2; mt++)
                    MMA_F16(sacc[mt][nt], a[mt][0], a[mt][1], a[mt][2], a[mt][3],
                            b[nt][0], b[nt][1]);
        }

        // ---- online softmax ----
#pragma unroll
        for (int mt = 0; mt < 2; mt++)
#pragma unroll
            for (int rr = 0; rr < 2; rr++) {
                float mx = -1e30f;
#pragma unroll
                for (int nt = 0; nt < 8; nt++)
#pragma unroll
                    for (int cc = 0; cc < 2; cc++) {
                        float v = sacc[mt][nt][rr * 2 + cc] * ATT_SCALE;
                        int col = k0 + nt * 8 + 2 * tig + cc;
                        v = (col < len) ? v : -1e30f;
                        sacc[mt][nt][rr * 2 + cc] = v;
                        mx = fmaxf(mx, v);
                    }
                mx = fmaxf(mx, __shfl_xor_sync(0xffffffffu, mx, 1));
                mx = fmaxf(mx, __shfl_xor_sync(0xffffffffu, mx, 2));
                float mn = fmaxf(m[mt][rr], mx);
                float sf = __expf(m[mt][rr] - mn);
                m[mt][rr] = mn;
                float sum = 0.f;
#pragma unroll
                for (int nt = 0; nt < 8; nt++)
#pragma unroll
                    for (int cc = 0; cc < 2; cc++) {
                        float p = __expf(sacc[mt][nt][rr * 2 + cc] - mn);
                        sacc[mt][nt][rr * 2 + cc] = p;
                        sum += p;
                    }
                sum += __shfl_xor_sync(0xffffffffu, sum, 1);
                sum += __shfl_xor_sync(0xffffffffu, sum, 2);
                l[mt][rr] = l[mt][rr] * sf + sum;
#pragma unroll
                for (int nt = 0; nt < 8; nt++)
#pragma unroll
                    for (int cc = 0; cc < 2; cc++) oacc[mt][nt][rr * 2 + cc] *= sf;
            }

        // ---- O += P @ V (P via registers) ----
#pragma unroll
        for (int js = 0; js < 4; js++) {
            uint32_t pa[2][4];
#pragma unroll
            for (int mt = 0; mt < 2; mt++) {
                pa[mt][0] = packh2(sacc[mt][2 * js][0], sacc[mt][2 * js][1]);
                pa[mt][1] = packh2(sacc[mt][2 * js][2], sacc[mt][2 * js][3]);
                pa[mt][2] = packh2(sacc[mt][2 * js + 1][0], sacc[mt][2 * js + 1][1]);
                pa[mt][3] = packh2(sacc[mt][2 * js + 1][2], sacc[mt][2 * js + 1][3]);
            }
            uint32_t b[8][2];
#pragma unroll
            for (int np = 0; np < 4; np++)
                ldsm_x4(b[2 * np][0], b[2 * np][1], b[2 * np + 1][0], b[2 * np + 1][1],
                        stV + (np * 16 * AP + js * 8) * 4 + bOff);
#pragma unroll
            for (int nt = 0; nt < 8; nt++)
#pragma unroll
                for (int mt = 0; mt < 2; mt++)
                    MMA_F16(oacc[mt][nt], pa[mt][0], pa[mt][1], pa[mt][2], pa[mt][3],
                            b[nt][0], b[nt][1]);
        }
    }

    // ---- normalize + store fp16 to g_attOH[n][t][h*64+e] ----
    const int h = bh & 15;
#pragma unroll
    for (int mt = 0; mt < 2; mt++) {
        float inv0 = 1.0f / l[mt][0];
        float inv1 = 1.0f / l[mt][1];
        int r0 = t0 + rb + mt * 16 + gr;
        __half* dst = g_attOH + ((size_t)nb * TQ + r0) * DD + h * DH;
#pragma unroll
        for (int nt = 0; nt < 8; nt++) {
            int col = nt * 8 + 2 * tig;
            *(__half2*)(dst + col) =
                __floats2half2_rn(oacc[mt][nt][0] * inv0, oacc[mt][nt][1] * inv0);
            *(__half2*)(dst + (size_t)8 * DD + col) =
                __floats2half2_rn(oacc[mt][nt][2] * inv1, oacc[mt][nt][3] * inv1);
        }
    }
}

// =========================================================================
extern "C" void kernel_launch(void* const* d_in, const int* in_sizes, int n_in,
                              void* d_out, int out_size) {
    const float* q   = (const float*)d_in[0];
    const float* kv  = (const float*)d_in[1];
    const int*   kvl = (const int*)d_in[2];
    const float* Wq  = (const float*)d_in[3];
    const float* bq  = (const float*)d_in[4];
    const float* Wkv = (const float*)d_in[5];
    const float* bkv = (const float*)d_in[6];
    const float* Wfc = (const float*)d_in[7];
    const float* bfc = (const float*)d_in[8];
    float* out = (float*)d_out;

    cudaFuncSetAttribute(hgemm<0>, cudaFuncAttributeMaxDynamicSharedMemorySize, HGEMM_SMEM);
    cudaFuncSetAttribute(hgemm<1>, cudaFuncAttributeMaxDynamicSharedMemorySize, HGEMM_SMEM);
    cudaFuncSetAttribute(hgemm<2>, cudaFuncAttributeMaxDynamicSharedMemorySize, HGEMM_SMEM);
    cudaFuncSetAttribute(attn_h, cudaFuncAttributeMaxDynamicSharedMemorySize, ATTN_SMEM);

    // 1. transposes + weight converts
    transpose_h<TQ, 0><<<dim3(TQ / 32, DD / 32, NB), 256>>>(q);
    transpose_h<TKK, 1><<<dim3(TKK / 32, DD / 32, NB), 256>>>(kv);
    convert_h<0><<<(DD * DD / 4 + 255) / 256, 256>>>(Wq, DD * DD / 4);
    convert_h<1><<<(2 * DD * DD / 4 + 255) / 256, 256>>>(Wkv, 2 * DD * DD / 4);
    convert_h<2><<<(DD * DD / 4 + 255) / 256, 256>>>(Wfc, DD * DD / 4);

    // 2. projections
    hgemm<0><<<dim3(TQ / 128, DD / 128, NB), 256, HGEMM_SMEM>>>(bq, nullptr);
    hgemm<1><<<dim3(TKK / 128, 2 * DD / 128, NB), 256, HGEMM_SMEM>>>(bkv, nullptr);
    // 3. attention
    attn_h<<<dim3(TQ / 128, NB * NH), 128, ATTN_SMEM>>>(kvl);
    // 4. fc
    hgemm<2><<<dim3(DD / 128, TQ / 128, NB), 256, HGEMM_SMEM>>>(bfc, out);
}

// round 10
// speedup vs baseline: 6.4308x; 1.0024x over previous
#include <cuda_runtime.h>
#include <cuda_fp16.h>
#include <cstdint>

#define NB 8
#define TQ 512
#define TKK 1024
#define NH 16
#define DH 64
#define DD 1024
#define ATT_SCALE 0.015625f   // H/D = 16/1024

// ---------------- device scratch (fp16) ----------------
__device__ __half g_qT[NB * TQ * DD];        // [n,t,c]
__device__ __half g_kvT[NB * TKK * DD];      // [n,t,c]
__device__ __half g_WqH[DD * DD];            // [d,c]
__device__ __half g_WkvH[2 * DD * DD];       // [d,c]
__device__ __half g_WfcH[DD * DD];           // [o,c]
__device__ __half g_QhH[NB * NH * TQ * DH];  // [n,h,t,e]
__device__ __half g_KhH[NB * NH * TKK * DH]; // [n,h,k,e]
__device__ __half g_VtH[NB * NH * DH * TKK]; // [n,h,e,k]  (transposed V)
__device__ __half g_attOH[NB * TQ * DD];     // [n,t,d], d=h*64+e

// ---------------- helpers ----------------
#define MMA_F16(d, a0, a1, a2, a3, b0, b1)                                    \
    asm volatile(                                                             \
        "mma.sync.aligned.m16n8k16.row.col.f32.f16.f16.f32 "                  \
        "{%0,%1,%2,%3}, {%4,%5,%6,%7}, {%8,%9}, {%0,%1,%2,%3};\n"             \
        : "+f"(d[0]), "+f"(d[1]), "+f"(d[2]), "+f"(d[3])                      \
        : "r"(a0), "r"(a1), "r"(a2), "r"(a3), "r"(b0), "r"(b1))

__device__ __forceinline__ void ldsm_x4(uint32_t& r0, uint32_t& r1,
                                        uint32_t& r2, uint32_t& r3,
                                        uint32_t addr) {
    asm volatile("ldmatrix.sync.aligned.m8n8.x4.shared.b16 {%0,%1,%2,%3}, [%4];"
                 : "=r"(r0), "=r"(r1), "=r"(r2), "=r"(r3) : "r"(addr));
}

__device__ __forceinline__ void cp16(uint32_t dst, const void* src) {
    asm volatile("cp.async.cg.shared.global [%0], [%1], 16;\n" ::"r"(dst), "l"(src));
}
#define CP_COMMIT() asm volatile("cp.async.commit_group;\n" ::)
#define CP_WAIT2()  asm volatile("cp.async.wait_group 2;\n" ::)
#define CP_WAIT1()  asm volatile("cp.async.wait_group 1;\n" ::)
#define CP_WAIT0()  asm volatile("cp.async.wait_group 0;\n" ::)

__device__ __forceinline__ uint32_t packh2(float lo, float hi) {
    __half2 h = __floats2half2_rn(lo, hi);
    return *reinterpret_cast<uint32_t*>(&h);
}

// =========================================================================
// transpose + convert: src [n][DD][TD] f32 -> g_qT/g_kvT [n][TD][DD] fp16
// =========================================================================
template <int TD, int DSTSEL>
__global__ __launch_bounds__(256) void transpose_h(const float* __restrict__ src) {
    __shared__ float tile[32][33];
    const int nb = blockIdx.z, c0 = blockIdx.y * 32, t0 = blockIdx.x * 32;
    const float* s = src + (size_t)nb * DD * TD;
    __half* d = (DSTSEL == 0 ? g_qT : g_kvT) + (size_t)nb * TD * DD;
    const int tx = threadIdx.x & 31, ty = threadIdx.x >> 5;
#pragma unroll
    for (int i = 0; i < 4; i++)
        tile[ty + 8 * i][tx] = s[(size_t)(c0 + ty + 8 * i) * TD + t0 + tx];
    __syncthreads();
#pragma unroll
    for (int i = 0; i < 4; i++)
        d[(size_t)(t0 + ty + 8 * i) * DD + c0 + tx] =
            __float2half_rn(tile[tx][ty + 8 * i]);
}

// fused fp32 -> fp16 convert of Wq | Wkv | Wfc (one launch)
__global__ void convert_all(const float* __restrict__ Wq,
                            const float* __restrict__ Wkv,
                            const float* __restrict__ Wfc) {
    const int N1 = DD * DD / 4;           // Wq float4 count
    const int N2 = N1 + 2 * DD * DD / 4;  // + Wkv
    const int NT = N2 + DD * DD / 4;      // + Wfc
    int i = blockIdx.x * blockDim.x + threadIdx.x;
    if (i >= NT) return;
    const float* s;
    __half* d;
    int j;
    if (i < N1)       { s = Wq;  d = g_WqH;  j = i; }
    else if (i < N2)  { s = Wkv; d = g_WkvH; j = i - N1; }
    else              { s = Wfc; d = g_WfcH; j = i - N2; }
    float4 v = ((const float4*)s)[j];
    __half2* dd = (__half2*)d + j * 2;
    dd[0] = __floats2half2_rn(v.x, v.y);
    dd[1] = __floats2half2_rn(v.z, v.w);
}

// =========================================================================
// fp16 GEMM 128x128, BK=32, cp.async 4-stage, ldmatrix fragment loads.
// 256 thr = 8 warps (2m x 4n), warp tile 64x32.
// MODE 0: Q proj -> g_QhH.  MODE 1: KV proj -> g_KhH/g_VtH.  MODE 2: FC.
// =========================================================================
#define HP 20                      // smem row pitch in 32-bit words (40 fp16)
#define HTILE_W (128 * HP)
#define HSTG_W (2 * HTILE_W)
#define HGEMM_SMEM (4 * HSTG_W * 4)  // 81920 B

template <int MODE>
__global__ __launch_bounds__(256, 2) void hgemm(
    const float* __restrict__ bias, float* __restrict__ out) {
    extern __shared__ uint32_t sw[];
    const uint32_t sbase = (uint32_t)__cvta_generic_to_shared(sw);

    const int nb = blockIdx.z;
    const int m0 = blockIdx.x * 128;
    const int n0 = blockIdx.y * 128;
    const int tid = threadIdx.x;
    const int lane = tid & 31, wid = tid >> 5;
    const int gr = lane >> 2, tig = lane & 3;
    const int warp_m = wid & 1, warp_n = wid >> 1;

    const uint32_t aOff = ((lane & 15) * HP + ((lane >> 4) & 1) * 4) * 4;
    const uint32_t bOff =
        (((lane & 7) + ((lane >> 4) & 1) * 8) * HP + ((lane >> 3) & 1) * 4) * 4;

    const __half* Asrc = (MODE == 0) ? g_qT + (size_t)nb * TQ * DD
                       : (MODE == 1) ? g_kvT + (size_t)nb * TKK * DD
                                     : g_WfcH;
    const __half* Bsrc = (MODE == 0) ? g_WqH
                       : (MODE == 1) ? g_WkvH
                                     : g_attOH + (size_t)nb * TQ * DD;

    float acc[4][4][4];
#pragma unroll
    for (int mt = 0; mt < 4; mt++)
#pragma unroll
        for (int nt = 0; nt < 4; nt++)
#pragma unroll
            for (int i = 0; i < 4; i++) acc[mt][nt][i] = 0.f;

    const int ca0 = tid * 2;
    auto issue = [&](int s, int kb) {
        const uint32_t stA = sbase + s * (HSTG_W * 4);
        const uint32_t stB = stA + HTILE_W * 4;
#pragma unroll
        for (int u = 0; u < 2; u++) {
            int ca = ca0 + u;
            int r = ca >> 2, ch = ca & 3;
            cp16(stA + (r * HP + ch * 4) * 4,
                 Asrc + (size_t)(m0 + r) * DD + kb * 32 + ch * 8);
            cp16(stB + (r * HP + ch * 4) * 4,
                 Bsrc + (size_t)(n0 + r) * DD + kb * 32 + ch * 8);
        }
    };

    issue(0, 0); CP_COMMIT();
    issue(1, 1); CP_COMMIT();
    issue(2, 2); CP_COMMIT();

    const int KB = DD / 32;   // 32
    for (int kb = 0; kb < KB; kb++) {
        if (kb + 2 < KB)      { CP_WAIT2(); }
        else if (kb + 1 < KB) { CP_WAIT1(); }
        else                  { CP_WAIT0(); }
        __syncthreads();
        if (kb + 3 < KB) { issue((kb + 3) & 3, kb + 3); CP_COMMIT(); }

        const uint32_t stA = sbase + (kb & 3) * (HSTG_W * 4);
        const uint32_t stB = stA + HTILE_W * 4;
#pragma unroll
        for (int ks = 0; ks < 2; ks++) {        // two k16 steps
            const int kw = ks * 8;
            uint32_t a[4][4];
#pragma unroll
            for (int mt = 0; mt < 4; mt++)
                ldsm_x4(a[mt][0], a[mt][1], a[mt][2], a[mt][3],
                        stA + ((warp_m * 64 + mt * 16) * HP + kw) * 4 + aOff);
            uint32_t b[4][2];
#pragma unroll
            for (int np = 0; np < 2; np++)
                ldsm_x4(b[2 * np][0], b[2 * np][1], b[2 * np + 1][0], b[2 * np + 1][1],
                        stB + ((warp_n * 32 + np * 16) * HP + kw) * 4 + bOff);
#pragma unroll
            for (int nt = 0; nt < 4; nt++)
#pragma unroll
                for (int mt = 0; mt < 4; mt++)
                    MMA_F16(acc[mt][nt], a[mt][0], a[mt][1], a[mt][2], a[mt][3],
                            b[nt][0], b[nt][1]);
        }
    }

    // ---- epilogue ----
#pragma unroll
    for (int mt = 0; mt < 4; mt++) {
        int row = m0 + warp_m * 64 + mt * 16 + gr;
#pragma unroll
        for (int nt = 0; nt < 4; nt++) {
            int col = n0 + warp_n * 32 + nt * 8 + 2 * tig;
            if (MODE == 2) {
                float b0v = bias[row], b8v = bias[row + 8];
                float* o0 = out + ((size_t)nb * DD + row) * TQ + col;
                *(float2*)o0 = make_float2(acc[mt][nt][0] + b0v, acc[mt][nt][1] + b0v);
                *(float2*)(o0 + (size_t)8 * TQ) =
                    make_float2(acc[mt][nt][2] + b8v, acc[mt][nt][3] + b8v);
            } else {
                float2 bv = *(const float2*)(bias + col);
                float v0 = acc[mt][nt][0] + bv.x, v1 = acc[mt][nt][1] + bv.y;
                float v2 = acc[mt][nt][2] + bv.x, v3 = acc[mt][nt][3] + bv.y;
                if (MODE == 0) {
                    int h = col >> 6, e = col & 63;
                    __half* dst = g_QhH + ((size_t)(nb * NH + h) * TQ + row) * DH + e;
                    *(__half2*)dst = __floats2half2_rn(v0, v1);
                    *(__half2*)(dst + 8 * DH) = __floats2half2_rn(v2, v3);
                } else {
                    int h = col >> 7, e = col & 127;
                    if (e < 64) {
                        __half* dst = g_KhH + ((size_t)(nb * NH + h) * TKK + row) * DH + e;
                        *(__half2*)dst = __floats2half2_rn(v0, v1);
                        *(__half2*)(dst + 8 * DH) = __floats2half2_rn(v2, v3);
                    } else {
                        int ee = e - 64;
                        __half* hb = g_VtH + ((size_t)(nb * NH + h) * DH + ee) * TKK;
                        hb[row] = __float2half_rn(v0);
                        hb[TKK + row] = __float2half_rn(v1);
                        hb[row + 8] = __float2half_rn(v2);
                        hb[TKK + row + 8] = __float2half_rn(v3);
                    }
                }
            }
        }
    }
}

// =========================================================================
// fp16 flash attention. Br=128, Bc=64, 256 threads = 8 warps x 16 q-rows.
// ldmatrix loads, cp.async double-buffered K/V, register P-passing.
// =========================================================================
#define AP 36
#define KV_STG_W (128 * AP)
#define ATTN_SMEM ((128 * AP + 2 * KV_STG_W) * 4)   // 55296 B

__global__ __launch_bounds__(256, 2) void attn_h(const int* __restrict__ kv_len) {
    extern __shared__ uint32_t sw[];
    const uint32_t sbase = (uint32_t)__cvta_generic_to_shared(sw);
    uint32_t* Qs = sw;

    const int bh = blockIdx.y;
    const int nb = bh >> 4;
    const int t0 = blockIdx.x * 128;
    const int len = kv_len[nb];

    const __half* Qg = g_QhH + ((size_t)bh * TQ + t0) * DH;
    const __half* Kg = g_KhH + (size_t)bh * TKK * DH;
    const __half* Vt = g_VtH + (size_t)bh * DH * TKK;

    const int tid = threadIdx.x;
    const int w = tid >> 5, lane = tid & 31;
    const int gr = lane >> 2, tig = lane & 3;
    const int rb = w * 16;                 // 16 q-rows per warp

    const uint32_t aOff = ((lane & 15) * AP + ((lane >> 4) & 1) * 4) * 4;
    const uint32_t bOff =
        (((lane & 7) + ((lane >> 4) & 1) * 8) * AP + ((lane >> 3) & 1) * 4) * 4;

    // Q tile once: 128 rows x 8 chunks = 1024 / 256 thr
#pragma unroll
    for (int u = 0; u < 4; u++) {
        int lin = tid + u * 256;
        int row = lin >> 3, ch = lin & 7;
        uint4 v = *(const uint4*)(Qg + (size_t)row * DH + ch * 8);
        *(uint4*)(Qs + row * AP + ch * 4) = v;
    }

    auto issueKV = [&](int kt, int s) {
        const uint32_t stK = sbase + (128 * AP + s * KV_STG_W) * 4;
        const uint32_t stV = stK + 64 * AP * 4;
        const int k0 = kt * 64;
#pragma unroll
        for (int u = 0; u < 2; u++) {
            int lin = tid + u * 256;
            int row = lin >> 3, ch = lin & 7;
            cp16(stK + (row * AP + ch * 4) * 4,
                 Kg + (size_t)(k0 + row) * DH + ch * 8);
            cp16(stV + (row * AP + ch * 4) * 4,
                 Vt + (size_t)row * TKK + k0 + ch * 8);
        }
    };

    float m[2], l[2], oacc[8][4];
    m[0] = m[1] = -1e30f;
    l[0] = l[1] = 0.f;
#pragma unroll
    for (int nt = 0; nt < 8; nt++)
#pragma unroll
        for (int i = 0; i < 4; i++) oacc[nt][i] = 0.f;

    const int ktiles = (len + 63) >> 6;
    issueKV(0, 0); CP_COMMIT();

    for (int kt = 0; kt < ktiles; kt++) {
        const int k0 = kt * 64;
        const int st = kt & 1;
        __syncthreads();
        if (kt + 1 < ktiles) { issueKV(kt + 1, st ^ 1); CP_COMMIT(); CP_WAIT1(); }
        else                 { CP_WAIT0(); }
        __syncthreads();

        const uint32_t stK = sbase + (128 * AP + st * KV_STG_W) * 4;
        const uint32_t stV = stK + 64 * AP * 4;

        // ---- S = Q @ K^T ----
        float sacc[8][4];
#pragma unroll
        for (int nt = 0; nt < 8; nt++)
#pragma unroll
            for (int i = 0; i < 4; i++) sacc[nt][i] = 0.f;

#pragma unroll
        for (int es = 0; es < 4; es++) {
            const int ew = es * 8;
            uint32_t a0, a1, a2, a3;
            ldsm_x4(a0, a1, a2, a3, sbase + (rb * AP + ew) * 4 + aOff);
            uint32_t b[8][2];
#pragma unroll
            for (int np = 0; np < 4; np++)
                ldsm_x4(b[2 * np][0], b[2 * np][1], b[2 * np + 1][0], b[2 * np + 1][1],
                        stK + (np * 16 * AP + ew) * 4 + bOff);
#pragma unroll
            for (int nt = 0; nt < 8; nt++)
                MMA_F16(sacc[nt], a0, a1, a2, a3, b[nt][0], b[nt][1]);
        }

        // ---- online softmax ----
#pragma unroll
        for (int rr = 0; rr < 2; rr++) {
            float mx = -1e30f;
#pragma unroll
            for (int nt = 0; nt < 8; nt++)
#pragma unroll
                for (int cc = 0; cc < 2; cc++) {
                    float v = sacc[nt][rr * 2 + cc] * ATT_SCALE;
                    int col = k0 + nt * 8 + 2 * tig + cc;
                    v = (col < len) ? v : -1e30f;
                    sacc[nt][rr * 2 + cc] = v;
                    mx = fmaxf(mx, v);
                }
            mx = fmaxf(mx, __shfl_xor_sync(0xffffffffu, mx, 1));
            mx = fmaxf(mx, __shfl_xor_sync(0xffffffffu, mx, 2));
            float mn = fmaxf(m[rr], mx);
            float sf = __expf(m[rr] - mn);
            m[rr] = mn;
            float sum = 0.f;
#pragma unroll
            for (int nt = 0; nt < 8; nt++)
#pragma unroll
                for (int cc = 0; cc < 2; cc++) {
                    float p = __expf(sacc[nt][rr * 2 + cc] - mn);
                    sacc[nt][rr * 2 + cc] = p;
                    sum += p;
                }
            sum += __shfl_xor_sync(0xffffffffu, sum, 1);
            sum += __shfl_xor_sync(0xffffffffu, sum, 2);
            l[rr] = l[rr] * sf + sum;
#pragma unroll
            for (int nt = 0; nt < 8; nt++)
#pragma unroll
                for (int cc = 0; cc < 2; cc++) oacc[nt][rr * 2 + cc] *= sf;
        }

        // ---- O += P @ V (P via registers) ----
#pragma unroll
        for (int js = 0; js < 4; js++) {
            uint32_t pa0 = packh2(sacc[2 * js][0], sacc[2 * js][1]);
            uint32_t pa1 = packh2(sacc[2 * js][2], sacc[2 * js][3]);
            uint32_t pa2 = packh2(sacc[2 * js + 1][0], sacc[2 * js + 1][1]);
            uint32_t pa3 = packh2(sacc[2 * js + 1][2], sacc[2 * js + 1][3]);
            uint32_t b[8][2];
#pragma unroll
            for (int np = 0; np < 4; np++)
                ldsm_x4(b[2 * np][0], b[2 * np][1], b[2 * np + 1][0], b[2 * np + 1][1],
                        stV + (np * 16 * AP + js * 8) * 4 + bOff);
#pragma unroll
            for (int nt = 0; nt < 8; nt++)
                MMA_F16(oacc[nt], pa0, pa1, pa2, pa3, b[nt][0], b[nt][1]);
        }
    }

    // ---- normalize + store fp16 to g_attOH[n][t][h*64+e] ----
    const int h = bh & 15;
    float inv0 = 1.0f / l[0];
    float inv1 = 1.0f / l[1];
    int r0 = t0 + rb + gr;
    __half* dst = g_attOH + ((size_t)nb * TQ + r0) * DD + h * DH;
#pragma unroll
    for (int nt = 0; nt < 8; nt++) {
        int col = nt * 8 + 2 * tig;
        *(__half2*)(dst + col) =
            __floats2half2_rn(oacc[nt][0] * inv0, oacc[nt][1] * inv0);
        *(__half2*)(dst + (size_t)8 * DD + col) =
            __floats2half2_rn(oacc[nt][2] * inv1, oacc[nt][3] * inv1);
    }
}

// =========================================================================
extern "C" void kernel_launch(void* const* d_in, const int* in_sizes, int n_in,
                              void* d_out, int out_size) {
    const float* q   = (const float*)d_in[0];
    const float* kv  = (const float*)d_in[1];
    const int*   kvl = (const int*)d_in[2];
    const float* Wq  = (const float*)d_in[3];
    const float* bq  = (const float*)d_in[4];
    const float* Wkv = (const float*)d_in[5];
    const float* bkv = (const float*)d_in[6];
    const float* Wfc = (const float*)d_in[7];
    const float* bfc = (const float*)d_in[8];
    float* out = (float*)d_out;

    cudaFuncSetAttribute(hgemm<0>, cudaFuncAttributeMaxDynamicSharedMemorySize, HGEMM_SMEM);
    cudaFuncSetAttribute(hgemm<1>, cudaFuncAttributeMaxDynamicSharedMemorySize, HGEMM_SMEM);
    cudaFuncSetAttribute(hgemm<2>, cudaFuncAttributeMaxDynamicSharedMemorySize, HGEMM_SMEM);
    cudaFuncSetAttribute(attn_h, cudaFuncAttributeMaxDynamicSharedMemorySize, ATTN_SMEM);

    // 1. transposes + fused weight convert
    transpose_h<TQ, 0><<<dim3(TQ / 32, DD / 32, NB), 256>>>(q);
    transpose_h<TKK, 1><<<dim3(TKK / 32, DD / 32, NB), 256>>>(kv);
    convert_all<<<(DD * DD + 255) / 256, 256>>>(Wq, Wkv, Wfc);

    // 2. projections
    hgemm<0><<<dim3(TQ / 128, DD / 128, NB), 256, HGEMM_SMEM>>>(bq, nullptr);
    hgemm<1><<<dim3(TKK / 128, 2 * DD / 128, NB), 256, HGEMM_SMEM>>>(bkv, nullptr);
    // 3. attention
    attn_h<<<dim3(TQ / 128, NB * NH), 256, ATTN_SMEM>>>(kvl);
    // 4. fc
    hgemm<2><<<dim3(DD / 128, TQ / 128, NB), 256, HGEMM_SMEM>>>(bfc, out);
}

// round 11
// speedup vs baseline: 7.6880x; 1.1955x over previous
#include <cuda_runtime.h>
#include <cuda_fp16.h>
#include <cstdint>

#define NB 8
#define TQ 512
#define TKK 1024
#define NH 16
#define DH 64
#define DD 1024
#define ATT_SCALE 0.015625f   // H/D = 16/1024

// ---------------- device scratch (fp16) ----------------
__device__ __half g_qT[NB * TQ * DD];        // [n,t,c]
__device__ __half g_kvT[NB * TKK * DD];      // [n,t,c]
__device__ __half g_WqH[DD * DD];            // [d,c]
__device__ __half g_WkvH[2 * DD * DD];       // [d,c]
__device__ __half g_WfcH[DD * DD];           // [o,c]
__device__ __half g_QhH[NB * NH * TQ * DH];  // [n,h,t,e]
__device__ __half g_KhH[NB * NH * TKK * DH]; // [n,h,k,e]
__device__ __half g_VtH[NB * NH * DH * TKK]; // [n,h,e,k]  (transposed V)
__device__ __half g_attOH[NB * TQ * DD];     // [n,t,d], d=h*64+e

// ---------------- helpers ----------------
#define MMA_F16(d, a0, a1, a2, a3, b0, b1)                                    \
    asm volatile(                                                             \
        "mma.sync.aligned.m16n8k16.row.col.f32.f16.f16.f32 "                  \
        "{%0,%1,%2,%3}, {%4,%5,%6,%7}, {%8,%9}, {%0,%1,%2,%3};\n"             \
        : "+f"(d[0]), "+f"(d[1]), "+f"(d[2]), "+f"(d[3])                      \
        : "r"(a0), "r"(a1), "r"(a2), "r"(a3), "r"(b0), "r"(b1))

__device__ __forceinline__ void ldsm_x4(uint32_t& r0, uint32_t& r1,
                                        uint32_t& r2, uint32_t& r3,
                                        uint32_t addr) {
    asm volatile("ldmatrix.sync.aligned.m8n8.x4.shared.b16 {%0,%1,%2,%3}, [%4];"
                 : "=r"(r0), "=r"(r1), "=r"(r2), "=r"(r3) : "r"(addr));
}

__device__ __forceinline__ void cp16(uint32_t dst, const void* src) {
    asm volatile("cp.async.cg.shared.global [%0], [%1], 16;\n" ::"r"(dst), "l"(src));
}
#define CP_COMMIT() asm volatile("cp.async.commit_group;\n" ::)
#define CP_WAIT1()  asm volatile("cp.async.wait_group 1;\n" ::)
#define CP_WAIT0()  asm volatile("cp.async.wait_group 0;\n" ::)

__device__ __forceinline__ uint32_t packh2(float lo, float hi) {
    __half2 h = __floats2half2_rn(lo, hi);
    return *reinterpret_cast<uint32_t*>(&h);
}

// =========================================================================
// transpose + convert: src [n][DD][TD] f32 -> g_qT/g_kvT [n][TD][DD] fp16
// =========================================================================
template <int TD, int DSTSEL>
__global__ __launch_bounds__(256) void transpose_h(const float* __restrict__ src) {
    __shared__ float tile[32][33];
    const int nb = blockIdx.z, c0 = blockIdx.y * 32, t0 = blockIdx.x * 32;
    const float* s = src + (size_t)nb * DD * TD;
    __half* d = (DSTSEL == 0 ? g_qT : g_kvT) + (size_t)nb * TD * DD;
    const int tx = threadIdx.x & 31, ty = threadIdx.x >> 5;
#pragma unroll
    for (int i = 0; i < 4; i++)
        tile[ty + 8 * i][tx] = s[(size_t)(c0 + ty + 8 * i) * TD + t0 + tx];
    __syncthreads();
#pragma unroll
    for (int i = 0; i < 4; i++)
        d[(size_t)(t0 + ty + 8 * i) * DD + c0 + tx] =
            __float2half_rn(tile[tx][ty + 8 * i]);
}

// fused fp32 -> fp16 convert of Wq | Wkv | Wfc (one launch)
__global__ void convert_all(const float* __restrict__ Wq,
                            const float* __restrict__ Wkv,
                            const float* __restrict__ Wfc) {
    const int N1 = DD * DD / 4;
    const int N2 = N1 + 2 * DD * DD / 4;
    const int NT = N2 + DD * DD / 4;
    int i = blockIdx.x * blockDim.x + threadIdx.x;
    if (i >= NT) return;
    const float* s;
    __half* d;
    int j;
    if (i < N1)       { s = Wq;  d = g_WqH;  j = i; }
    else if (i < N2)  { s = Wkv; d = g_WkvH; j = i - N1; }
    else              { s = Wfc; d = g_WfcH; j = i - N2; }
    float4 v = ((const float4*)s)[j];
    __half2* dd = (__half2*)d + j * 2;
    dd[0] = __floats2half2_rn(v.x, v.y);
    dd[1] = __floats2half2_rn(v.z, v.w);
}

// =========================================================================
// fp16 GEMM 128x128, BK=64 per stage, 3-stage cp.async, ONE sync per stage.
// 256 thr = 8 warps (2m x 4n), warp tile 64x32, ldmatrix fragment loads.
// MODE 0: Q proj -> g_QhH.  MODE 1: KV proj -> g_KhH/g_VtH.  MODE 2: FC.
// =========================================================================
#define HP2 36                       // smem row pitch in words (144 B: 64 fp16 + pad)
#define H2TILE_B (128 * HP2 * 4)     // 18432 B per tile
#define H2STG_B  (2 * H2TILE_B)      // 36864 B per stage (A+B)
#define HGEMM_SMEM (3 * H2STG_B)     // 110592 B

template <int MODE>
__global__ __launch_bounds__(256, 2) void hgemm(
    const float* __restrict__ bias, float* __restrict__ out) {
    extern __shared__ uint32_t sw[];
    const uint32_t sbase = (uint32_t)__cvta_generic_to_shared(sw);

    const int nb = blockIdx.z;
    const int m0 = blockIdx.x * 128;
    const int n0 = blockIdx.y * 128;
    const int tid = threadIdx.x;
    const int lane = tid & 31, wid = tid >> 5;
    const int gr = lane >> 2, tig = lane & 3;
    const int warp_m = wid & 1, warp_n = wid >> 1;

    const uint32_t aOff = ((lane & 15) * HP2 + ((lane >> 4) & 1) * 4) * 4;
    const uint32_t bOff =
        (((lane & 7) + ((lane >> 4) & 1) * 8) * HP2 + ((lane >> 3) & 1) * 4) * 4;

    const __half* Asrc = (MODE == 0) ? g_qT + (size_t)nb * TQ * DD
                       : (MODE == 1) ? g_kvT + (size_t)nb * TKK * DD
                                     : g_WfcH;
    const __half* Bsrc = (MODE == 0) ? g_WqH
                       : (MODE == 1) ? g_WkvH
                                     : g_attOH + (size_t)nb * TQ * DD;

    float acc[4][4][4];
#pragma unroll
    for (int mt = 0; mt < 4; mt++)
#pragma unroll
        for (int nt = 0; nt < 4; nt++)
#pragma unroll
            for (int i = 0; i < 4; i++) acc[mt][nt][i] = 0.f;

    // per-stage copy: 2 tiles x (128 rows x 8 chunks of 16B) = 2048 chunks,
    // 8 per thread (4 A + 4 B)
    auto issue = [&](int s, int kc) {
        const uint32_t stA = sbase + s * H2STG_B;
        const uint32_t stB = stA + H2TILE_B;
#pragma unroll
        for (int u = 0; u < 4; u++) {
            int ca = u * 256 + tid;
            int r = ca >> 3, ch = ca & 7;
            uint32_t soff = (r * HP2 + ch * 4) * 4;
            cp16(stA + soff, Asrc + (size_t)(m0 + r) * DD + kc * 64 + ch * 8);
            cp16(stB + soff, Bsrc + (size_t)(n0 + r) * DD + kc * 64 + ch * 8);
        }
    };

    issue(0, 0); CP_COMMIT();
    issue(1, 1); CP_COMMIT();

    const int KB = DD / 64;   // 16
    for (int kb = 0; kb < KB; kb++) {
        if (kb + 1 < KB) { CP_WAIT1(); } else { CP_WAIT0(); }
        __syncthreads();
        // safe: stage (kb+2)%3 was last read at iteration kb-1, ordered by the
        // barrier above
        if (kb + 2 < KB) { issue((kb + 2) % 3, kb + 2); CP_COMMIT(); }

        const uint32_t stA = sbase + (kb % 3) * H2STG_B;
        const uint32_t stB = stA + H2TILE_B;
#pragma unroll
        for (int ks = 0; ks < 4; ks++) {        // four k16 steps
            const int kw = ks * 8;
            uint32_t a[4][4];
#pragma unroll
            for (int mt = 0; mt < 4; mt++)
                ldsm_x4(a[mt][0], a[mt][1], a[mt][2], a[mt][3],
                        stA + ((warp_m * 64 + mt * 16) * HP2 + kw) * 4 + aOff);
            uint32_t b[4][2];
#pragma unroll
            for (int np = 0; np < 2; np++)
                ldsm_x4(b[2 * np][0], b[2 * np][1], b[2 * np + 1][0], b[2 * np + 1][1],
                        stB + ((warp_n * 32 + np * 16) * HP2 + kw) * 4 + bOff);
#pragma unroll
            for (int nt = 0; nt < 4; nt++)
#pragma unroll
                for (int mt = 0; mt < 4; mt++)
                    MMA_F16(acc[mt][nt], a[mt][0], a[mt][1], a[mt][2], a[mt][3],
                            b[nt][0], b[nt][1]);
        }
    }

    // ---- epilogue ----
#pragma unroll
    for (int mt = 0; mt < 4; mt++) {
        int row = m0 + warp_m * 64 + mt * 16 + gr;
#pragma unroll
        for (int nt = 0; nt < 4; nt++) {
            int col = n0 + warp_n * 32 + nt * 8 + 2 * tig;
            if (MODE == 2) {
                float b0v = bias[row], b8v = bias[row + 8];
                float* o0 = out + ((size_t)nb * DD + row) * TQ + col;
                *(float2*)o0 = make_float2(acc[mt][nt][0] + b0v, acc[mt][nt][1] + b0v);
                *(float2*)(o0 + (size_t)8 * TQ) =
                    make_float2(acc[mt][nt][2] + b8v, acc[mt][nt][3] + b8v);
            } else {
                float2 bv = *(const float2*)(bias + col);
                float v0 = acc[mt][nt][0] + bv.x, v1 = acc[mt][nt][1] + bv.y;
                float v2 = acc[mt][nt][2] + bv.x, v3 = acc[mt][nt][3] + bv.y;
                if (MODE == 0) {
                    int h = col >> 6, e = col & 63;
                    __half* dst = g_QhH + ((size_t)(nb * NH + h) * TQ + row) * DH + e;
                    *(__half2*)dst = __floats2half2_rn(v0, v1);
                    *(__half2*)(dst + 8 * DH) = __floats2half2_rn(v2, v3);
                } else {
                    int h = col >> 7, e = col & 127;
                    if (e < 64) {
                        __half* dst = g_KhH + ((size_t)(nb * NH + h) * TKK + row) * DH + e;
                        *(__half2*)dst = __floats2half2_rn(v0, v1);
                        *(__half2*)(dst + 8 * DH) = __floats2half2_rn(v2, v3);
                    } else {
                        int ee = e - 64;
                        __half* hb = g_VtH + ((size_t)(nb * NH + h) * DH + ee) * TKK;
                        hb[row] = __float2half_rn(v0);
                        hb[TKK + row] = __float2half_rn(v1);
                        hb[row + 8] = __float2half_rn(v2);
                        hb[TKK + row + 8] = __float2half_rn(v3);
                    }
                }
            }
        }
    }
}

// =========================================================================
// fp16 flash attention. Br=128, Bc=64, 256 threads = 8 warps x 16 q-rows.
// ldmatrix loads, cp.async double-buffered K/V, register P-passing.
// =========================================================================
#define AP 36
#define KV_STG_W (128 * AP)
#define ATTN_SMEM ((128 * AP + 2 * KV_STG_W) * 4)   // 55296 B

__global__ __launch_bounds__(256, 2) void attn_h(const int* __restrict__ kv_len) {
    extern __shared__ uint32_t sw[];
    const uint32_t sbase = (uint32_t)__cvta_generic_to_shared(sw);
    uint32_t* Qs = sw;

    const int bh = blockIdx.y;
    const int nb = bh >> 4;
    const int t0 = blockIdx.x * 128;
    const int len = kv_len[nb];

    const __half* Qg = g_QhH + ((size_t)bh * TQ + t0) * DH;
    const __half* Kg = g_KhH + (size_t)bh * TKK * DH;
    const __half* Vt = g_VtH + (size_t)bh * DH * TKK;

    const int tid = threadIdx.x;
    const int w = tid >> 5, lane = tid & 31;
    const int gr = lane >> 2, tig = lane & 3;
    const int rb = w * 16;

    const uint32_t aOff = ((lane & 15) * AP + ((lane >> 4) & 1) * 4) * 4;
    const uint32_t bOff =
        (((lane & 7) + ((lane >> 4) & 1) * 8) * AP + ((lane >> 3) & 1) * 4) * 4;

#pragma unroll
    for (int u = 0; u < 4; u++) {
        int lin = tid + u * 256;
        int row = lin >> 3, ch = lin & 7;
        uint4 v = *(const uint4*)(Qg + (size_t)row * DH + ch * 8);
        *(uint4*)(Qs + row * AP + ch * 4) = v;
    }

    auto issueKV = [&](int kt, int s) {
        const uint32_t stK = sbase + (128 * AP + s * KV_STG_W) * 4;
        const uint32_t stV = stK + 64 * AP * 4;
        const int k0 = kt * 64;
#pragma unroll
        for (int u = 0; u < 2; u++) {
            int lin = tid + u * 256;
            int row = lin >> 3, ch = lin & 7;
            cp16(stK + (row * AP + ch * 4) * 4,
                 Kg + (size_t)(k0 + row) * DH + ch * 8);
            cp16(stV + (row * AP + ch * 4) * 4,
                 Vt + (size_t)row * TKK + k0 + ch * 8);
        }
    };

    float m[2], l[2], oacc[8][4];
    m[0] = m[1] = -1e30f;
    l[0] = l[1] = 0.f;
#pragma unroll
    for (int nt = 0; nt < 8; nt++)
#pragma unroll
        for (int i = 0; i < 4; i++) oacc[nt][i] = 0.f;

    const int ktiles = (len + 63) >> 6;
    issueKV(0, 0); CP_COMMIT();

    for (int kt = 0; kt < ktiles; kt++) {
        const int k0 = kt * 64;
        const int st = kt & 1;
        __syncthreads();
        if (kt + 1 < ktiles) { issueKV(kt + 1, st ^ 1); CP_COMMIT(); CP_WAIT1(); }
        else                 { CP_WAIT0(); }
        __syncthreads();

        const uint32_t stK = sbase + (128 * AP + st * KV_STG_W) * 4;
        const uint32_t stV = stK + 64 * AP * 4;

        // ---- S = Q @ K^T ----
        float sacc[8][4];
#pragma unroll
        for (int nt = 0; nt < 8; nt++)
#pragma unroll
            for (int i = 0; i < 4; i++) sacc[nt][i] = 0.f;

#pragma unroll
        for (int es = 0; es < 4; es++) {
            const int ew = es * 8;
            uint32_t a0, a1, a2, a3;
            ldsm_x4(a0, a1, a2, a3, sbase + (rb * AP + ew) * 4 + aOff);
            uint32_t b[8][2];
#pragma unroll
            for (int np = 0; np < 4; np++)
                ldsm_x4(b[2 * np][0], b[2 * np][1], b[2 * np + 1][0], b[2 * np + 1][1],
                        stK + (np * 16 * AP + ew) * 4 + bOff);
#pragma unroll
            for (int nt = 0; nt < 8; nt++)
                MMA_F16(sacc[nt], a0, a1, a2, a3, b[nt][0], b[nt][1]);
        }

        // ---- online softmax ----
#pragma unroll
        for (int rr = 0; rr < 2; rr++) {
            float mx = -1e30f;
#pragma unroll
            for (int nt = 0; nt < 8; nt++)
#pragma unroll
                for (int cc = 0; cc < 2; cc++) {
                    float v = sacc[nt][rr * 2 + cc] * ATT_SCALE;
                    int col = k0 + nt * 8 + 2 * tig + cc;
                    v = (col < len) ? v : -1e30f;
                    sacc[nt][rr * 2 + cc] = v;
                    mx = fmaxf(mx, v);
                }
            mx = fmaxf(mx, __shfl_xor_sync(0xffffffffu, mx, 1));
            mx = fmaxf(mx, __shfl_xor_sync(0xffffffffu, mx, 2));
            float mn = fmaxf(m[rr], mx);
            float sf = __expf(m[rr] - mn);
            m[rr] = mn;
            float sum = 0.f;
#pragma unroll
            for (int nt = 0; nt < 8; nt++)
#pragma unroll
                for (int cc = 0; cc < 2; cc++) {
                    float p = __expf(sacc[nt][rr * 2 + cc] - mn);
                    sacc[nt][rr * 2 + cc] = p;
                    sum += p;
                }
            sum += __shfl_xor_sync(0xffffffffu, sum, 1);
            sum += __shfl_xor_sync(0xffffffffu, sum, 2);
            l[rr] = l[rr] * sf + sum;
#pragma unroll
            for (int nt = 0; nt < 8; nt++)
#pragma unroll
                for (int cc = 0; cc < 2; cc++) oacc[nt][rr * 2 + cc] *= sf;
        }

        // ---- O += P @ V (P via registers) ----
#pragma unroll
        for (int js = 0; js < 4; js++) {
            uint32_t pa0 = packh2(sacc[2 * js][0], sacc[2 * js][1]);
            uint32_t pa1 = packh2(sacc[2 * js][2], sacc[2 * js][3]);
            uint32_t pa2 = packh2(sacc[2 * js + 1][0], sacc[2 * js + 1][1]);
            uint32_t pa3 = packh2(sacc[2 * js + 1][2], sacc[2 * js + 1][3]);
            uint32_t b[8][2];
#pragma unroll
            for (int np = 0; np < 4; np++)
                ldsm_x4(b[2 * np][0], b[2 * np][1], b[2 * np + 1][0], b[2 * np + 1][1],
                        stV + (np * 16 * AP + js * 8) * 4 + bOff);
#pragma unroll
            for (int nt = 0; nt < 8; nt++)
                MMA_F16(oacc[nt], pa0, pa1, pa2, pa3, b[nt][0], b[nt][1]);
        }
    }

    // ---- normalize + store fp16 to g_attOH[n][t][h*64+e] ----
    const int h = bh & 15;
    float inv0 = 1.0f / l[0];
    float inv1 = 1.0f / l[1];
    int r0 = t0 + rb + gr;
    __half* dst = g_attOH + ((size_t)nb * TQ + r0) * DD + h * DH;
#pragma unroll
    for (int nt = 0; nt < 8; nt++) {
        int col = nt * 8 + 2 * tig;
        *(__half2*)(dst + col) =
            __floats2half2_rn(oacc[nt][0] * inv0, oacc[nt][1] * inv0);
        *(__half2*)(dst + (size_t)8 * DD + col) =
            __floats2half2_rn(oacc[nt][2] * inv1, oacc[nt][3] * inv1);
    }
}

// =========================================================================
extern "C" void kernel_launch(void* const* d_in, const int* in_sizes, int n_in,
                              void* d_out, int out_size) {
    const float* q   = (const float*)d_in[0];
    const float* kv  = (const float*)d_in[1];
    const int*   kvl = (const int*)d_in[2];
    const float* Wq  = (const float*)d_in[3];
    const float* bq  = (const float*)d_in[4];
    const float* Wkv = (const float*)d_in[5];
    const float* bkv = (const float*)d_in[6];
    const float* Wfc = (const float*)d_in[7];
    const float* bfc = (const float*)d_in[8];
    float* out = (float*)d_out;

    cudaFuncSetAttribute(hgemm<0>, cudaFuncAttributeMaxDynamicSharedMemorySize, HGEMM_SMEM);
    cudaFuncSetAttribute(hgemm<1>, cudaFuncAttributeMaxDynamicSharedMemorySize, HGEMM_SMEM);
    cudaFuncSetAttribute(hgemm<2>, cudaFuncAttributeMaxDynamicSharedMemorySize, HGEMM_SMEM);
    cudaFuncSetAttribute(attn_h, cudaFuncAttributeMaxDynamicSharedMemorySize, ATTN_SMEM);

    // 1. transposes + fused weight convert
    transpose_h<TQ, 0><<<dim3(TQ / 32, DD / 32, NB), 256>>>(q);
    transpose_h<TKK, 1><<<dim3(TKK / 32, DD / 32, NB), 256>>>(kv);
    convert_all<<<(DD * DD + 255) / 256, 256>>>(Wq, Wkv, Wfc);

    // 2. projections
    hgemm<0><<<dim3(TQ / 128, DD / 128, NB), 256, HGEMM_SMEM>>>(bq, nullptr);
    hgemm<1><<<dim3(TKK / 128, 2 * DD / 128, NB), 256, HGEMM_SMEM>>>(bkv, nullptr);
    // 3. attention
    attn_h<<<dim3(TQ / 128, NB * NH), 256, ATTN_SMEM>>>(kvl);
    // 4. fc
    hgemm<2><<<dim3(DD / 128, TQ / 128, NB), 256, HGEMM_SMEM>>>(bfc, out);
}

// round 12
// speedup vs baseline: 7.8554x; 1.0218x over previous
#include <cuda_runtime.h>
#include <cuda_fp16.h>
#include <cstdint>

#define NB 8
#define TQ 512
#define TKK 1024
#define NH 16
#define DH 64
#define DD 1024
#define ATT_SCALE 0.015625f   // H/D = 16/1024

// ---------------- device scratch (fp16) ----------------
__device__ __half g_qT[NB * TQ * DD];        // [n,t,c]
__device__ __half g_kvT[NB * TKK * DD];      // [n,t,c]
__device__ __half g_WqH[DD * DD];            // [d,c]
__device__ __half g_WkvH[2 * DD * DD];       // [d,c]
__device__ __half g_WfcH[DD * DD];           // [o,c]
__device__ __half g_QhH[NB * NH * TQ * DH];  // [n,h,t,e]
__device__ __half g_KhH[NB * NH * TKK * DH]; // [n,h,k,e]
__device__ __half g_VtH[NB * NH * DH * TKK]; // [n,h,e,k]  (transposed V)
__device__ __half g_attOH[NB * TQ * DD];     // [n,t,d], d=h*64+e

// ---------------- helpers ----------------
#define MMA_F16(d, a0, a1, a2, a3, b0, b1)                                    \
    asm volatile(                                                             \
        "mma.sync.aligned.m16n8k16.row.col.f32.f16.f16.f32 "                  \
        "{%0,%1,%2,%3}, {%4,%5,%6,%7}, {%8,%9}, {%0,%1,%2,%3};\n"             \
        : "+f"(d[0]), "+f"(d[1]), "+f"(d[2]), "+f"(d[3])                      \
        : "r"(a0), "r"(a1), "r"(a2), "r"(a3), "r"(b0), "r"(b1))

__device__ __forceinline__ void ldsm_x4(uint32_t& r0, uint32_t& r1,
                                        uint32_t& r2, uint32_t& r3,
                                        uint32_t addr) {
    asm volatile("ldmatrix.sync.aligned.m8n8.x4.shared.b16 {%0,%1,%2,%3}, [%4];"
                 : "=r"(r0), "=r"(r1), "=r"(r2), "=r"(r3) : "r"(addr));
}

__device__ __forceinline__ void cp16(uint32_t dst, const void* src) {
    asm volatile("cp.async.cg.shared.global [%0], [%1], 16;\n" ::"r"(dst), "l"(src));
}
#define CP_COMMIT() asm volatile("cp.async.commit_group;\n" ::)
#define CP_WAIT1()  asm volatile("cp.async.wait_group 1;\n" ::)
#define CP_WAIT0()  asm volatile("cp.async.wait_group 0;\n" ::)

__device__ __forceinline__ uint32_t packh2(float lo, float hi) {
    __half2 h = __floats2half2_rn(lo, hi);
    return *reinterpret_cast<uint32_t*>(&h);
}

// =========================================================================
// merged transpose + convert: q and kv in one launch.
// z < NB: q batch z (TD=TQ, x<16 active). z >= NB: kv batch z-NB (TD=TKK).
// =========================================================================
__global__ __launch_bounds__(256) void transpose_all(
    const float* __restrict__ q, const float* __restrict__ kv) {
    __shared__ float tile[32][33];
    const int z = blockIdx.z;
    const bool isQ = z < NB;
    const int TD = isQ ? TQ : TKK;
    if (isQ && blockIdx.x >= TQ / 32) return;
    const int nb = isQ ? z : z - NB;
    const int c0 = blockIdx.y * 32, t0 = blockIdx.x * 32;
    const float* s = (isQ ? q : kv) + (size_t)nb * DD * TD;
    __half* d = (isQ ? g_qT : g_kvT) + (size_t)nb * TD * DD;
    const int tx = threadIdx.x & 31, ty = threadIdx.x >> 5;
#pragma unroll
    for (int i = 0; i < 4; i++)
        tile[ty + 8 * i][tx] = s[(size_t)(c0 + ty + 8 * i) * TD + t0 + tx];
    __syncthreads();
#pragma unroll
    for (int i = 0; i < 4; i++)
        d[(size_t)(t0 + ty + 8 * i) * DD + c0 + tx] =
            __float2half_rn(tile[tx][ty + 8 * i]);
}

// fused fp32 -> fp16 convert of Wq | Wkv | Wfc (one launch)
__global__ void convert_all(const float* __restrict__ Wq,
                            const float* __restrict__ Wkv,
                            const float* __restrict__ Wfc) {
    const int N1 = DD * DD / 4;
    const int N2 = N1 + 2 * DD * DD / 4;
    const int NT = N2 + DD * DD / 4;
    int i = blockIdx.x * blockDim.x + threadIdx.x;
    if (i >= NT) return;
    const float* s;
    __half* d;
    int j;
    if (i < N1)       { s = Wq;  d = g_WqH;  j = i; }
    else if (i < N2)  { s = Wkv; d = g_WkvH; j = i - N1; }
    else              { s = Wfc; d = g_WfcH; j = i - N2; }
    float4 v = ((const float4*)s)[j];
    __half2* dd = (__half2*)d + j * 2;
    dd[0] = __floats2half2_rn(v.x, v.y);
    dd[1] = __floats2half2_rn(v.z, v.w);
}

// =========================================================================
// Shared GEMM mainloop: 128x128 block, BK=64/stage, 3-stage cp.async,
// one __syncthreads per stage. 256 thr = 8 warps (2m x 4n), warp tile 64x32.
// =========================================================================
#define HP2 36                       // smem row pitch in words (144 B)
#define H2TILE_B (128 * HP2 * 4)     // 18432 B per tile
#define H2STG_B  (2 * H2TILE_B)      // 36864 B per stage
#define HGEMM_SMEM (3 * H2STG_B)     // 110592 B

__device__ __forceinline__ void gemm_mainloop(
    const __half* __restrict__ Asrc, const __half* __restrict__ Bsrc,
    uint32_t sbase, int m0, int n0, int tid, int warp_m, int warp_n,
    uint32_t aOff, uint32_t bOff, float acc[4][4][4]) {

    auto issue = [&](int s, int kc) {
        const uint32_t stA = sbase + s * H2STG_B;
        const uint32_t stB = stA + H2TILE_B;
#pragma unroll
        for (int u = 0; u < 4; u++) {
            int ca = u * 256 + tid;
            int r = ca >> 3, ch = ca & 7;
            uint32_t soff = (r * HP2 + ch * 4) * 4;
            cp16(stA + soff, Asrc + (size_t)(m0 + r) * DD + kc * 64 + ch * 8);
            cp16(stB + soff, Bsrc + (size_t)(n0 + r) * DD + kc * 64 + ch * 8);
        }
    };

    issue(0, 0); CP_COMMIT();
    issue(1, 1); CP_COMMIT();

    const int KB = DD / 64;   // 16
    for (int kb = 0; kb < KB; kb++) {
        if (kb + 1 < KB) { CP_WAIT1(); } else { CP_WAIT0(); }
        __syncthreads();
        if (kb + 2 < KB) { issue((kb + 2) % 3, kb + 2); CP_COMMIT(); }

        const uint32_t stA = sbase + (kb % 3) * H2STG_B;
        const uint32_t stB = stA + H2TILE_B;
#pragma unroll
        for (int ks = 0; ks < 4; ks++) {
            const int kw = ks * 8;
            uint32_t a[4][4];
#pragma unroll
            for (int mt = 0; mt < 4; mt++)
                ldsm_x4(a[mt][0], a[mt][1], a[mt][2], a[mt][3],
                        stA + ((warp_m * 64 + mt * 16) * HP2 + kw) * 4 + aOff);
            uint32_t b[4][2];
#pragma unroll
            for (int np = 0; np < 2; np++)
                ldsm_x4(b[2 * np][0], b[2 * np][1], b[2 * np + 1][0], b[2 * np + 1][1],
                        stB + ((warp_n * 32 + np * 16) * HP2 + kw) * 4 + bOff);
#pragma unroll
            for (int nt = 0; nt < 4; nt++)
#pragma unroll
                for (int mt = 0; mt < 4; mt++)
                    MMA_F16(acc[mt][nt], a[mt][0], a[mt][1], a[mt][2], a[mt][3],
                            b[nt][0], b[nt][1]);
        }
    }
}

// =========================================================================
// Merged projection kernel: grid.x = 160 tiles (32 Q + 128 KV), grid.z = NB.
// Tile order keeps same-n tiles adjacent for B-operand L2 reuse.
// =========================================================================
__global__ __launch_bounds__(256, 2) void proj_all(
    const float* __restrict__ bq, const float* __restrict__ bkv) {
    extern __shared__ uint32_t sw[];
    const uint32_t sbase = (uint32_t)__cvta_generic_to_shared(sw);

    const int nb = blockIdx.z;
    const int bx = blockIdx.x;
    const int tid = threadIdx.x;
    const int lane = tid & 31, wid = tid >> 5;
    const int gr = lane >> 2, tig = lane & 3;
    const int warp_m = wid & 1, warp_n = wid >> 1;

    const uint32_t aOff = ((lane & 15) * HP2 + ((lane >> 4) & 1) * 4) * 4;
    const uint32_t bOff =
        (((lane & 7) + ((lane >> 4) & 1) * 8) * HP2 + ((lane >> 3) & 1) * 4) * 4;

    int mode, m0, n0;
    const __half *Asrc, *Bsrc;
    const float* bias;
    if (bx < 32) {                      // Q projection: 4 m-tiles x 8 n-tiles
        mode = 0;
        m0 = (bx & 3) * 128;
        n0 = (bx >> 2) * 128;
        Asrc = g_qT + (size_t)nb * TQ * DD;
        Bsrc = g_WqH;
        bias = bq;
    } else {                            // KV projection: 8 m-tiles x 16 n-tiles
        mode = 1;
        int kx = bx - 32;
        m0 = (kx & 7) * 128;
        n0 = (kx >> 3) * 128;
        Asrc = g_kvT + (size_t)nb * TKK * DD;
        Bsrc = g_WkvH;
        bias = bkv;
    }

    float acc[4][4][4];
#pragma unroll
    for (int mt = 0; mt < 4; mt++)
#pragma unroll
        for (int nt = 0; nt < 4; nt++)
#pragma unroll
            for (int i = 0; i < 4; i++) acc[mt][nt][i] = 0.f;

    gemm_mainloop(Asrc, Bsrc, sbase, m0, n0, tid, warp_m, warp_n, aOff, bOff, acc);

    // ---- epilogue ----
#pragma unroll
    for (int mt = 0; mt < 4; mt++) {
        int row = m0 + warp_m * 64 + mt * 16 + gr;
#pragma unroll
        for (int nt = 0; nt < 4; nt++) {
            int col = n0 + warp_n * 32 + nt * 8 + 2 * tig;
            float2 bv = *(const float2*)(bias + col);
            float v0 = acc[mt][nt][0] + bv.x, v1 = acc[mt][nt][1] + bv.y;
            float v2 = acc[mt][nt][2] + bv.x, v3 = acc[mt][nt][3] + bv.y;
            if (mode == 0) {
                int h = col >> 6, e = col & 63;
                __half* dst = g_QhH + ((size_t)(nb * NH + h) * TQ + row) * DH + e;
                *(__half2*)dst = __floats2half2_rn(v0, v1);
                *(__half2*)(dst + 8 * DH) = __floats2half2_rn(v2, v3);
            } else {
                int h = col >> 7, e = col & 127;
                if (e < 64) {
                    __half* dst = g_KhH + ((size_t)(nb * NH + h) * TKK + row) * DH + e;
                    *(__half2*)dst = __floats2half2_rn(v0, v1);
                    *(__half2*)(dst + 8 * DH) = __floats2half2_rn(v2, v3);
                } else {
                    int ee = e - 64;
                    __half* hb = g_VtH + ((size_t)(nb * NH + h) * DH + ee) * TKK;
                    hb[row] = __float2half_rn(v0);
                    hb[TKK + row] = __float2half_rn(v1);
                    hb[row + 8] = __float2half_rn(v2);
                    hb[TKK + row + 8] = __float2half_rn(v3);
                }
            }
        }
    }
}

// =========================================================================
// FC kernel: out[n,o,t] = Wfc @ attO^T + bfc
// =========================================================================
__global__ __launch_bounds__(256, 2) void fc_gemm(
    const float* __restrict__ bias, float* __restrict__ out) {
    extern __shared__ uint32_t sw[];
    const uint32_t sbase = (uint32_t)__cvta_generic_to_shared(sw);

    const int nb = blockIdx.z;
    const int m0 = blockIdx.x * 128;
    const int n0 = blockIdx.y * 128;
    const int tid = threadIdx.x;
    const int lane = tid & 31, wid = tid >> 5;
    const int gr = lane >> 2, tig = lane & 3;
    const int warp_m = wid & 1, warp_n = wid >> 1;

    const uint32_t aOff = ((lane & 15) * HP2 + ((lane >> 4) & 1) * 4) * 4;
    const uint32_t bOff =
        (((lane & 7) + ((lane >> 4) & 1) * 8) * HP2 + ((lane >> 3) & 1) * 4) * 4;

    float acc[4][4][4];
#pragma unroll
    for (int mt = 0; mt < 4; mt++)
#pragma unroll
        for (int nt = 0; nt < 4; nt++)
#pragma unroll
            for (int i = 0; i < 4; i++) acc[mt][nt][i] = 0.f;

    gemm_mainloop(g_WfcH, g_attOH + (size_t)nb * TQ * DD,
                  sbase, m0, n0, tid, warp_m, warp_n, aOff, bOff, acc);

#pragma unroll
    for (int mt = 0; mt < 4; mt++) {
        int row = m0 + warp_m * 64 + mt * 16 + gr;
        float b0v = bias[row], b8v = bias[row + 8];
#pragma unroll
        for (int nt = 0; nt < 4; nt++) {
            int col = n0 + warp_n * 32 + nt * 8 + 2 * tig;
            float* o0 = out + ((size_t)nb * DD + row) * TQ + col;
            *(float2*)o0 = make_float2(acc[mt][nt][0] + b0v, acc[mt][nt][1] + b0v);
            *(float2*)(o0 + (size_t)8 * TQ) =
                make_float2(acc[mt][nt][2] + b8v, acc[mt][nt][3] + b8v);
        }
    }
}

// =========================================================================
// fp16 flash attention. Br=128, Bc=64, 256 threads = 8 warps x 16 q-rows.
// ldmatrix loads, cp.async double-buffered K/V, ONE barrier per tile.
// =========================================================================
#define AP 36
#define KV_STG_W (128 * AP)
#define ATTN_SMEM ((128 * AP + 2 * KV_STG_W) * 4)   // 55296 B

__global__ __launch_bounds__(256, 2) void attn_h(const int* __restrict__ kv_len) {
    extern __shared__ uint32_t sw[];
    const uint32_t sbase = (uint32_t)__cvta_generic_to_shared(sw);
    uint32_t* Qs = sw;

    const int bh = blockIdx.y;
    const int nb = bh >> 4;
    const int t0 = blockIdx.x * 128;
    const int len = kv_len[nb];

    const __half* Qg = g_QhH + ((size_t)bh * TQ + t0) * DH;
    const __half* Kg = g_KhH + (size_t)bh * TKK * DH;
    const __half* Vt = g_VtH + (size_t)bh * DH * TKK;

    const int tid = threadIdx.x;
    const int w = tid >> 5, lane = tid & 31;
    const int gr = lane >> 2, tig = lane & 3;
    const int rb = w * 16;

    const uint32_t aOff = ((lane & 15) * AP + ((lane >> 4) & 1) * 4) * 4;
    const uint32_t bOff =
        (((lane & 7) + ((lane >> 4) & 1) * 8) * AP + ((lane >> 3) & 1) * 4) * 4;

#pragma unroll
    for (int u = 0; u < 4; u++) {
        int lin = tid + u * 256;
        int row = lin >> 3, ch = lin & 7;
        uint4 v = *(const uint4*)(Qg + (size_t)row * DH + ch * 8);
        *(uint4*)(Qs + row * AP + ch * 4) = v;
    }

    auto issueKV = [&](int kt, int s) {
        const uint32_t stK = sbase + (128 * AP + s * KV_STG_W) * 4;
        const uint32_t stV = stK + 64 * AP * 4;
        const int k0 = kt * 64;
#pragma unroll
        for (int u = 0; u < 2; u++) {
            int lin = tid + u * 256;
            int row = lin >> 3, ch = lin & 7;
            cp16(stK + (row * AP + ch * 4) * 4,
                 Kg + (size_t)(k0 + row) * DH + ch * 8);
            cp16(stV + (row * AP + ch * 4) * 4,
                 Vt + (size_t)row * TKK + k0 + ch * 8);
        }
    };

    float m[2], l[2], oacc[8][4];
    m[0] = m[1] = -1e30f;
    l[0] = l[1] = 0.f;
#pragma unroll
    for (int nt = 0; nt < 8; nt++)
#pragma unroll
        for (int i = 0; i < 4; i++) oacc[nt][i] = 0.f;

    const int ktiles = (len + 63) >> 6;
    issueKV(0, 0); CP_COMMIT();

    for (int kt = 0; kt < ktiles; kt++) {
        const int k0 = kt * 64;
        const int st = kt & 1;
        CP_WAIT0();         // stage st (group kt) complete
        __syncthreads();    // orders prior tile's reads before overwriting st^1
        if (kt + 1 < ktiles) { issueKV(kt + 1, st ^ 1); CP_COMMIT(); }

        const uint32_t stK = sbase + (128 * AP + st * KV_STG_W) * 4;
        const uint32_t stV = stK + 64 * AP * 4;

        // ---- S = Q @ K^T ----
        float sacc[8][4];
#pragma unroll
        for (int nt = 0; nt < 8; nt++)
#pragma unroll
            for (int i = 0; i < 4; i++) sacc[nt][i] = 0.f;

#pragma unroll
        for (int es = 0; es < 4; es++) {
            const int ew = es * 8;
            uint32_t a0, a1, a2, a3;
            ldsm_x4(a0, a1, a2, a3, sbase + (rb * AP + ew) * 4 + aOff);
            uint32_t b[8][2];
#pragma unroll
            for (int np = 0; np < 4; np++)
                ldsm_x4(b[2 * np][0], b[2 * np][1], b[2 * np + 1][0], b[2 * np + 1][1],
                        stK + (np * 16 * AP + ew) * 4 + bOff);
#pragma unroll
            for (int nt = 0; nt < 8; nt++)
                MMA_F16(sacc[nt], a0, a1, a2, a3, b[nt][0], b[nt][1]);
        }

        // ---- online softmax ----
#pragma unroll
        for (int rr = 0; rr < 2; rr++) {
            float mx = -1e30f;
#pragma unroll
            for (int nt = 0; nt < 8; nt++)
#pragma unroll
                for (int cc = 0; cc < 2; cc++) {
                    float v = sacc[nt][rr * 2 + cc] * ATT_SCALE;
                    int col = k0 + nt * 8 + 2 * tig + cc;
                    v = (col < len) ? v : -1e30f;
                    sacc[nt][rr * 2 + cc] = v;
                    mx = fmaxf(mx, v);
                }
            mx = fmaxf(mx, __shfl_xor_sync(0xffffffffu, mx, 1));
            mx = fmaxf(mx, __shfl_xor_sync(0xffffffffu, mx, 2));
            float mn = fmaxf(m[rr], mx);
            float sf = __expf(m[rr] - mn);
            m[rr] = mn;
            float sum = 0.f;
#pragma unroll
            for (int nt = 0; nt < 8; nt++)
#pragma unroll
                for (int cc = 0; cc < 2; cc++) {
                    float p = __expf(sacc[nt][rr * 2 + cc] - mn);
                    sacc[nt][rr * 2 + cc] = p;
                    sum += p;
                }
            sum += __shfl_xor_sync(0xffffffffu, sum, 1);
            sum += __shfl_xor_sync(0xffffffffu, sum, 2);
            l[rr] = l[rr] * sf + sum;
#pragma unroll
            for (int nt = 0; nt < 8; nt++)
#pragma unroll
                for (int cc = 0; cc < 2; cc++) oacc[nt][rr * 2 + cc] *= sf;
        }

        // ---- O += P @ V (P via registers) ----
#pragma unroll
        for (int js = 0; js < 4; js++) {
            uint32_t pa0 = packh2(sacc[2 * js][0], sacc[2 * js][1]);
            uint32_t pa1 = packh2(sacc[2 * js][2], sacc[2 * js][3]);
            uint32_t pa2 = packh2(sacc[2 * js + 1][0], sacc[2 * js + 1][1]);
            uint32_t pa3 = packh2(sacc[2 * js + 1][2], sacc[2 * js + 1][3]);
            uint32_t b[8][2];
#pragma unroll
            for (int np = 0; np < 4; np++)
                ldsm_x4(b[2 * np][0], b[2 * np][1], b[2 * np + 1][0], b[2 * np + 1][1],
                        stV + (np * 16 * AP + js * 8) * 4 + bOff);
#pragma unroll
            for (int nt = 0; nt < 8; nt++)
                MMA_F16(oacc[nt], pa0, pa1, pa2, pa3, b[nt][0], b[nt][1]);
        }
    }

    // ---- normalize + store fp16 to g_attOH[n][t][h*64+e] ----
    const int h = bh & 15;
    float inv0 = 1.0f / l[0];
    float inv1 = 1.0f / l[1];
    int r0 = t0 + rb + gr;
    __half* dst = g_attOH + ((size_t)nb * TQ + r0) * DD + h * DH;
#pragma unroll
    for (int nt = 0; nt < 8; nt++) {
        int col = nt * 8 + 2 * tig;
        *(__half2*)(dst + col) =
            __floats2half2_rn(oacc[nt][0] * inv0, oacc[nt][1] * inv0);
        *(__half2*)(dst + (size_t)8 * DD + col) =
            __floats2half2_rn(oacc[nt][2] * inv1, oacc[nt][3] * inv1);
    }
}

// =========================================================================
extern "C" void kernel_launch(void* const* d_in, const int* in_sizes, int n_in,
                              void* d_out, int out_size) {
    const float* q   = (const float*)d_in[0];
    const float* kv  = (const float*)d_in[1];
    const int*   kvl = (const int*)d_in[2];
    const float* Wq  = (const float*)d_in[3];
    const float* bq  = (const float*)d_in[4];
    const float* Wkv = (const float*)d_in[5];
    const float* bkv = (const float*)d_in[6];
    const float* Wfc = (const float*)d_in[7];
    const float* bfc = (const float*)d_in[8];
    float* out = (float*)d_out;

    cudaFuncSetAttribute(proj_all, cudaFuncAttributeMaxDynamicSharedMemorySize, HGEMM_SMEM);
    cudaFuncSetAttribute(fc_gemm, cudaFuncAttributeMaxDynamicSharedMemorySize, HGEMM_SMEM);
    cudaFuncSetAttribute(attn_h, cudaFuncAttributeMaxDynamicSharedMemorySize, ATTN_SMEM);

    // 1. merged transposes + fused weight convert
    transpose_all<<<dim3(TKK / 32, DD / 32, 2 * NB), 256>>>(q, kv);
    convert_all<<<(DD * DD + 255) / 256, 256>>>(Wq, Wkv, Wfc);

    // 2. merged projections (32 Q-tiles + 128 KV-tiles per batch)
    proj_all<<<dim3(160, 1, NB), 256, HGEMM_SMEM>>>(bq, bkv);
    // 3. attention
    attn_h<<<dim3(TQ / 128, NB * NH), 256, ATTN_SMEM>>>(kvl);
    // 4. fc
    fc_gemm<<<dim3(DD / 128, TQ / 128, NB), 256, HGEMM_SMEM>>>(bfc, out);
}

// round 13
// speedup vs baseline: 7.9023x; 1.0060x over previous
#include <cuda_runtime.h>
#include <cuda_fp16.h>
#include <cstdint>

#define NB 8
#define TQ 512
#define TKK 1024
#define NH 16
#define DH 64
#define DD 1024
// Q pre-scale: (H/D) * log2(e) folded into the Q projection output
#define QSCALE 0.02254211743f   // 0.015625 * 1.4426950408889634

// ---------------- device scratch (fp16) ----------------
__device__ __half g_qT[NB * TQ * DD];        // [n,t,c]
__device__ __half g_kvT[NB * TKK * DD];      // [n,t,c]
__device__ __half g_WqH[DD * DD];            // [d,c]
__device__ __half g_WkvH[2 * DD * DD];       // [d,c]
__device__ __half g_WfcH[DD * DD];           // [o,c]
__device__ __half g_QhH[NB * NH * TQ * DH];  // [n,h,t,e]  (pre-scaled by QSCALE)
__device__ __half g_KhH[NB * NH * TKK * DH]; // [n,h,k,e]
__device__ __half g_VtH[NB * NH * DH * TKK]; // [n,h,e,k]  (transposed V)
__device__ __half g_attOH[NB * TQ * DD];     // [n,t,d], d=h*64+e

// ---------------- helpers ----------------
#define MMA_F16(d, a0, a1, a2, a3, b0, b1)                                    \
    asm volatile(                                                             \
        "mma.sync.aligned.m16n8k16.row.col.f32.f16.f16.f32 "                  \
        "{%0,%1,%2,%3}, {%4,%5,%6,%7}, {%8,%9}, {%0,%1,%2,%3};\n"             \
        : "+f"(d[0]), "+f"(d[1]), "+f"(d[2]), "+f"(d[3])                      \
        : "r"(a0), "r"(a1), "r"(a2), "r"(a3), "r"(b0), "r"(b1))

__device__ __forceinline__ void ldsm_x4(uint32_t& r0, uint32_t& r1,
                                        uint32_t& r2, uint32_t& r3,
                                        uint32_t addr) {
    asm volatile("ldmatrix.sync.aligned.m8n8.x4.shared.b16 {%0,%1,%2,%3}, [%4];"
                 : "=r"(r0), "=r"(r1), "=r"(r2), "=r"(r3) : "r"(addr));
}

__device__ __forceinline__ void cp16(uint32_t dst, const void* src) {
    asm volatile("cp.async.cg.shared.global [%0], [%1], 16;\n" ::"r"(dst), "l"(src));
}
#define CP_COMMIT() asm volatile("cp.async.commit_group;\n" ::)
#define CP_WAIT1()  asm volatile("cp.async.wait_group 1;\n" ::)
#define CP_WAIT0()  asm volatile("cp.async.wait_group 0;\n" ::)

__device__ __forceinline__ uint32_t packh2(float lo, float hi) {
    __half2 h = __floats2half2_rn(lo, hi);
    return *reinterpret_cast<uint32_t*>(&h);
}

__device__ __forceinline__ float ex2f(float x) {
    float r;
    asm("ex2.approx.f32 %0, %1;" : "=f"(r) : "f"(x));
    return r;
}

// =========================================================================
// merged transpose + convert: q and kv in one launch.
// =========================================================================
__global__ __launch_bounds__(256) void transpose_all(
    const float* __restrict__ q, const float* __restrict__ kv) {
    __shared__ float tile[32][33];
    const int z = blockIdx.z;
    const bool isQ = z < NB;
    const int TD = isQ ? TQ : TKK;
    if (isQ && blockIdx.x >= TQ / 32) return;
    const int nb = isQ ? z : z - NB;
    const int c0 = blockIdx.y * 32, t0 = blockIdx.x * 32;
    const float* s = (isQ ? q : kv) + (size_t)nb * DD * TD;
    __half* d = (isQ ? g_qT : g_kvT) + (size_t)nb * TD * DD;
    const int tx = threadIdx.x & 31, ty = threadIdx.x >> 5;
#pragma unroll
    for (int i = 0; i < 4; i++)
        tile[ty + 8 * i][tx] = s[(size_t)(c0 + ty + 8 * i) * TD + t0 + tx];
    __syncthreads();
#pragma unroll
    for (int i = 0; i < 4; i++)
        d[(size_t)(t0 + ty + 8 * i) * DD + c0 + tx] =
            __float2half_rn(tile[tx][ty + 8 * i]);
}

// fused fp32 -> fp16 convert of Wq | Wkv | Wfc (one launch)
__global__ void convert_all(const float* __restrict__ Wq,
                            const float* __restrict__ Wkv,
                            const float* __restrict__ Wfc) {
    const int N1 = DD * DD / 4;
    const int N2 = N1 + 2 * DD * DD / 4;
    const int NT = N2 + DD * DD / 4;
    int i = blockIdx.x * blockDim.x + threadIdx.x;
    if (i >= NT) return;
    const float* s;
    __half* d;
    int j;
    if (i < N1)       { s = Wq;  d = g_WqH;  j = i; }
    else if (i < N2)  { s = Wkv; d = g_WkvH; j = i - N1; }
    else              { s = Wfc; d = g_WfcH; j = i - N2; }
    float4 v = ((const float4*)s)[j];
    __half2* dd = (__half2*)d + j * 2;
    dd[0] = __floats2half2_rn(v.x, v.y);
    dd[1] = __floats2half2_rn(v.z, v.w);
}

// =========================================================================
// Shared GEMM mainloop: 128x128 block, BK=64/stage, 3-stage cp.async,
// one __syncthreads per stage. 256 thr = 8 warps (2m x 4n), warp tile 64x32.
// =========================================================================
#define HP2 36                       // smem row pitch in words (144 B)
#define H2TILE_B (128 * HP2 * 4)     // 18432 B per tile
#define H2STG_B  (2 * H2TILE_B)      // 36864 B per stage
#define HGEMM_SMEM (3 * H2STG_B)     // 110592 B

__device__ __forceinline__ void gemm_mainloop(
    const __half* __restrict__ Asrc, const __half* __restrict__ Bsrc,
    uint32_t sbase, int m0, int n0, int tid, int warp_m, int warp_n,
    uint32_t aOff, uint32_t bOff, float acc[4][4][4]) {

    auto issue = [&](int s, int kc) {
        const uint32_t stA = sbase + s * H2STG_B;
        const uint32_t stB = stA + H2TILE_B;
#pragma unroll
        for (int u = 0; u < 4; u++) {
            int ca = u * 256 + tid;
            int r = ca >> 3, ch = ca & 7;
            uint32_t soff = (r * HP2 + ch * 4) * 4;
            cp16(stA + soff, Asrc + (size_t)(m0 + r) * DD + kc * 64 + ch * 8);
            cp16(stB + soff, Bsrc + (size_t)(n0 + r) * DD + kc * 64 + ch * 8);
        }
    };

    issue(0, 0); CP_COMMIT();
    issue(1, 1); CP_COMMIT();

    const int KB = DD / 64;   // 16
    for (int kb = 0; kb < KB; kb++) {
        if (kb + 1 < KB) { CP_WAIT1(); } else { CP_WAIT0(); }
        __syncthreads();
        if (kb + 2 < KB) { issue((kb + 2) % 3, kb + 2); CP_COMMIT(); }

        const uint32_t stA = sbase + (kb % 3) * H2STG_B;
        const uint32_t stB = stA + H2TILE_B;
#pragma unroll
        for (int ks = 0; ks < 4; ks++) {
            const int kw = ks * 8;
            uint32_t a[4][4];
#pragma unroll
            for (int mt = 0; mt < 4; mt++)
                ldsm_x4(a[mt][0], a[mt][1], a[mt][2], a[mt][3],
                        stA + ((warp_m * 64 + mt * 16) * HP2 + kw) * 4 + aOff);
            uint32_t b[4][2];
#pragma unroll
            for (int np = 0; np < 2; np++)
                ldsm_x4(b[2 * np][0], b[2 * np][1], b[2 * np + 1][0], b[2 * np + 1][1],
                        stB + ((warp_n * 32 + np * 16) * HP2 + kw) * 4 + bOff);
#pragma unroll
            for (int nt = 0; nt < 4; nt++)
#pragma unroll
                for (int mt = 0; mt < 4; mt++)
                    MMA_F16(acc[mt][nt], a[mt][0], a[mt][1], a[mt][2], a[mt][3],
                            b[nt][0], b[nt][1]);
        }
    }
}

// =========================================================================
// Merged projection kernel: grid.x = 160 tiles (32 Q + 128 KV), grid.z = NB.
// Q output is pre-scaled by QSCALE (softmax runs in log2 domain).
// =========================================================================
__global__ __launch_bounds__(256, 2) void proj_all(
    const float* __restrict__ bq, const float* __restrict__ bkv) {
    extern __shared__ uint32_t sw[];
    const uint32_t sbase = (uint32_t)__cvta_generic_to_shared(sw);

    const int nb = blockIdx.z;
    const int bx = blockIdx.x;
    const int tid = threadIdx.x;
    const int lane = tid & 31, wid = tid >> 5;
    const int gr = lane >> 2, tig = lane & 3;
    const int warp_m = wid & 1, warp_n = wid >> 1;

    const uint32_t aOff = ((lane & 15) * HP2 + ((lane >> 4) & 1) * 4) * 4;
    const uint32_t bOff =
        (((lane & 7) + ((lane >> 4) & 1) * 8) * HP2 + ((lane >> 3) & 1) * 4) * 4;

    int mode, m0, n0;
    const __half *Asrc, *Bsrc;
    const float* bias;
    if (bx < 32) {
        mode = 0;
        m0 = (bx & 3) * 128;
        n0 = (bx >> 2) * 128;
        Asrc = g_qT + (size_t)nb * TQ * DD;
        Bsrc = g_WqH;
        bias = bq;
    } else {
        mode = 1;
        int kx = bx - 32;
        m0 = (kx & 7) * 128;
        n0 = (kx >> 3) * 128;
        Asrc = g_kvT + (size_t)nb * TKK * DD;
        Bsrc = g_WkvH;
        bias = bkv;
    }

    float acc[4][4][4];
#pragma unroll
    for (int mt = 0; mt < 4; mt++)
#pragma unroll
        for (int nt = 0; nt < 4; nt++)
#pragma unroll
            for (int i = 0; i < 4; i++) acc[mt][nt][i] = 0.f;

    gemm_mainloop(Asrc, Bsrc, sbase, m0, n0, tid, warp_m, warp_n, aOff, bOff, acc);

    // ---- epilogue ----
#pragma unroll
    for (int mt = 0; mt < 4; mt++) {
        int row = m0 + warp_m * 64 + mt * 16 + gr;
#pragma unroll
        for (int nt = 0; nt < 4; nt++) {
            int col = n0 + warp_n * 32 + nt * 8 + 2 * tig;
            float2 bv = *(const float2*)(bias + col);
            float v0 = acc[mt][nt][0] + bv.x, v1 = acc[mt][nt][1] + bv.y;
            float v2 = acc[mt][nt][2] + bv.x, v3 = acc[mt][nt][3] + bv.y;
            if (mode == 0) {
                v0 *= QSCALE; v1 *= QSCALE; v2 *= QSCALE; v3 *= QSCALE;
                int h = col >> 6, e = col & 63;
                __half* dst = g_QhH + ((size_t)(nb * NH + h) * TQ + row) * DH + e;
                *(__half2*)dst = __floats2half2_rn(v0, v1);
                *(__half2*)(dst + 8 * DH) = __floats2half2_rn(v2, v3);
            } else {
                int h = col >> 7, e = col & 127;
                if (e < 64) {
                    __half* dst = g_KhH + ((size_t)(nb * NH + h) * TKK + row) * DH + e;
                    *(__half2*)dst = __floats2half2_rn(v0, v1);
                    *(__half2*)(dst + 8 * DH) = __floats2half2_rn(v2, v3);
                } else {
                    int ee = e - 64;
                    __half* hb = g_VtH + ((size_t)(nb * NH + h) * DH + ee) * TKK;
                    hb[row] = __float2half_rn(v0);
                    hb[TKK + row] = __float2half_rn(v1);
                    hb[row + 8] = __float2half_rn(v2);
                    hb[TKK + row + 8] = __float2half_rn(v3);
                }
            }
        }
    }
}

// =========================================================================
// FC kernel: out[n,o,t] = Wfc @ attO^T + bfc
// =========================================================================
__global__ __launch_bounds__(256, 2) void fc_gemm(
    const float* __restrict__ bias, float* __restrict__ out) {
    extern __shared__ uint32_t sw[];
    const uint32_t sbase = (uint32_t)__cvta_generic_to_shared(sw);

    const int nb = blockIdx.z;
    const int m0 = blockIdx.x * 128;
    const int n0 = blockIdx.y * 128;
    const int tid = threadIdx.x;
    const int lane = tid & 31, wid = tid >> 5;
    const int gr = lane >> 2, tig = lane & 3;
    const int warp_m = wid & 1, warp_n = wid >> 1;

    const uint32_t aOff = ((lane & 15) * HP2 + ((lane >> 4) & 1) * 4) * 4;
    const uint32_t bOff =
        (((lane & 7) + ((lane >> 4) & 1) * 8) * HP2 + ((lane >> 3) & 1) * 4) * 4;

    float acc[4][4][4];
#pragma unroll
    for (int mt = 0; mt < 4; mt++)
#pragma unroll
        for (int nt = 0; nt < 4; nt++)
#pragma unroll
            for (int i = 0; i < 4; i++) acc[mt][nt][i] = 0.f;

    gemm_mainloop(g_WfcH, g_attOH + (size_t)nb * TQ * DD,
                  sbase, m0, n0, tid, warp_m, warp_n, aOff, bOff, acc);

#pragma unroll
    for (int mt = 0; mt < 4; mt++) {
        int row = m0 + warp_m * 64 + mt * 16 + gr;
        float b0v = bias[row], b8v = bias[row + 8];
#pragma unroll
        for (int nt = 0; nt < 4; nt++) {
            int col = n0 + warp_n * 32 + nt * 8 + 2 * tig;
            float* o0 = out + ((size_t)nb * DD + row) * TQ + col;
            *(float2*)o0 = make_float2(acc[mt][nt][0] + b0v, acc[mt][nt][1] + b0v);
            *(float2*)(o0 + (size_t)8 * TQ) =
                make_float2(acc[mt][nt][2] + b8v, acc[mt][nt][3] + b8v);
        }
    }
}

// =========================================================================
// fp16 flash attention, base-2 softmax. Br=128, Bc=64, 256 thr = 8 warps.
// Interior tiles skip masking; ex2.approx; one barrier per tile.
// =========================================================================
#define AP 36
#define KV_STG_W (128 * AP)
#define ATTN_SMEM ((128 * AP + 2 * KV_STG_W) * 4)   // 55296 B

__global__ __launch_bounds__(256, 2) void attn_h(const int* __restrict__ kv_len) {
    extern __shared__ uint32_t sw[];
    const uint32_t sbase = (uint32_t)__cvta_generic_to_shared(sw);
    uint32_t* Qs = sw;

    const int bh = blockIdx.y;
    const int nb = bh >> 4;
    const int t0 = blockIdx.x * 128;
    const int len = kv_len[nb];

    const __half* Qg = g_QhH + ((size_t)bh * TQ + t0) * DH;
    const __half* Kg = g_KhH + (size_t)bh * TKK * DH;
    const __half* Vt = g_VtH + (size_t)bh * DH * TKK;

    const int tid = threadIdx.x;
    const int w = tid >> 5, lane = tid & 31;
    const int gr = lane >> 2, tig = lane & 3;
    const int rb = w * 16;

    const uint32_t aOff = ((lane & 15) * AP + ((lane >> 4) & 1) * 4) * 4;
    const uint32_t bOff =
        (((lane & 7) + ((lane >> 4) & 1) * 8) * AP + ((lane >> 3) & 1) * 4) * 4;

#pragma unroll
    for (int u = 0; u < 4; u++) {
        int lin = tid + u * 256;
        int row = lin >> 3, ch = lin & 7;
        uint4 v = *(const uint4*)(Qg + (size_t)row * DH + ch * 8);
        *(uint4*)(Qs + row * AP + ch * 4) = v;
    }

    auto issueKV = [&](int kt, int s) {
        const uint32_t stK = sbase + (128 * AP + s * KV_STG_W) * 4;
        const uint32_t stV = stK + 64 * AP * 4;
        const int k0 = kt * 64;
#pragma unroll
        for (int u = 0; u < 2; u++) {
            int lin = tid + u * 256;
            int row = lin >> 3, ch = lin & 7;
            cp16(stK + (row * AP + ch * 4) * 4,
                 Kg + (size_t)(k0 + row) * DH + ch * 8);
            cp16(stV + (row * AP + ch * 4) * 4,
                 Vt + (size_t)row * TKK + k0 + ch * 8);
        }
    };

    float m[2], l[2], oacc[8][4];
    m[0] = m[1] = -1e30f;
    l[0] = l[1] = 0.f;
#pragma unroll
    for (int nt = 0; nt < 8; nt++)
#pragma unroll
        for (int i = 0; i < 4; i++) oacc[nt][i] = 0.f;

    const int ktiles = (len + 63) >> 6;
    issueKV(0, 0); CP_COMMIT();

    for (int kt = 0; kt < ktiles; kt++) {
        const int k0 = kt * 64;
        const int st = kt & 1;
        CP_WAIT0();
        __syncthreads();
        if (kt + 1 < ktiles) { issueKV(kt + 1, st ^ 1); CP_COMMIT(); }

        const uint32_t stK = sbase + (128 * AP + st * KV_STG_W) * 4;
        const uint32_t stV = stK + 64 * AP * 4;

        // ---- S = Q @ K^T  (Q pre-scaled by QSCALE -> S in log2 units) ----
        float sacc[8][4];
#pragma unroll
        for (int nt = 0; nt < 8; nt++)
#pragma unroll
            for (int i = 0; i < 4; i++) sacc[nt][i] = 0.f;

#pragma unroll
        for (int es = 0; es < 4; es++) {
            const int ew = es * 8;
            uint32_t a0, a1, a2, a3;
            ldsm_x4(a0, a1, a2, a3, sbase + (rb * AP + ew) * 4 + aOff);
            uint32_t b[8][2];
#pragma unroll
            for (int np = 0; np < 4; np++)
                ldsm_x4(b[2 * np][0], b[2 * np][1], b[2 * np + 1][0], b[2 * np + 1][1],
                        stK + (np * 16 * AP + ew) * 4 + bOff);
#pragma unroll
            for (int nt = 0; nt < 8; nt++)
                MMA_F16(sacc[nt], a0, a1, a2, a3, b[nt][0], b[nt][1]);
        }

        // ---- online softmax (base 2) ----
        const bool partial = (k0 + 64 > len);
        if (partial) {
            // mask out-of-range columns once
#pragma unroll
            for (int nt = 0; nt < 8; nt++)
#pragma unroll
                for (int i = 0; i < 4; i++) {
                    int col = k0 + nt * 8 + 2 * tig + (i & 1);
                    if (col >= len) sacc[nt][i] = -1e30f;
                }
        }
#pragma unroll
        for (int rr = 0; rr < 2; rr++) {
            float mx = -1e30f;
#pragma unroll
            for (int nt = 0; nt < 8; nt++) {
                mx = fmaxf(mx, fmaxf(sacc[nt][rr * 2], sacc[nt][rr * 2 + 1]));
            }
            mx = fmaxf(mx, __shfl_xor_sync(0xffffffffu, mx, 1));
            mx = fmaxf(mx, __shfl_xor_sync(0xffffffffu, mx, 2));
            float mn = fmaxf(m[rr], mx);
            float sf = ex2f(m[rr] - mn);
            m[rr] = mn;
            float sum = 0.f;
#pragma unroll
            for (int nt = 0; nt < 8; nt++)
#pragma unroll
                for (int cc = 0; cc < 2; cc++) {
                    float p = ex2f(sacc[nt][rr * 2 + cc] - mn);
                    sacc[nt][rr * 2 + cc] = p;
                    sum += p;
                }
            sum += __shfl_xor_sync(0xffffffffu, sum, 1);
            sum += __shfl_xor_sync(0xffffffffu, sum, 2);
            l[rr] = l[rr] * sf + sum;
#pragma unroll
            for (int nt = 0; nt < 8; nt++)
#pragma unroll
                for (int cc = 0; cc < 2; cc++) oacc[nt][rr * 2 + cc] *= sf;
        }

        // ---- O += P @ V (P via registers) ----
#pragma unroll
        for (int js = 0; js < 4; js++) {
            uint32_t pa0 = packh2(sacc[2 * js][0], sacc[2 * js][1]);
            uint32_t pa1 = packh2(sacc[2 * js][2], sacc[2 * js][3]);
            uint32_t pa2 = packh2(sacc[2 * js + 1][0], sacc[2 * js + 1][1]);
            uint32_t pa3 = packh2(sacc[2 * js + 1][2], sacc[2 * js + 1][3]);
            uint32_t b[8][2];
#pragma unroll
            for (int np = 0; np < 4; np++)
                ldsm_x4(b[2 * np][0], b[2 * np][1], b[2 * np + 1][0], b[2 * np + 1][1],
                        stV + (np * 16 * AP + js * 8) * 4 + bOff);
#pragma unroll
            for (int nt = 0; nt < 8; nt++)
                MMA_F16(oacc[nt], pa0, pa1, pa2, pa3, b[nt][0], b[nt][1]);
        }
    }

    // ---- normalize + store fp16 to g_attOH[n][t][h*64+e] ----
    const int h = bh & 15;
    float inv0 = 1.0f / l[0];
    float inv1 = 1.0f / l[1];
    int r0 = t0 + rb + gr;
    __half* dst = g_attOH + ((size_t)nb * TQ + r0) * DD + h * DH;
#pragma unroll
    for (int nt = 0; nt < 8; nt++) {
        int col = nt * 8 + 2 * tig;
        *(__half2*)(dst + col) =
            __floats2half2_rn(oacc[nt][0] * inv0, oacc[nt][1] * inv0);
        *(__half2*)(dst + (size_t)8 * DD + col) =
            __floats2half2_rn(oacc[nt][2] * inv1, oacc[nt][3] * inv1);
    }
}

// =========================================================================
extern "C" void kernel_launch(void* const* d_in, const int* in_sizes, int n_in,
                              void* d_out, int out_size) {
    const float* q   = (const float*)d_in[0];
    const float* kv  = (const float*)d_in[1];
    const int*   kvl = (const int*)d_in[2];
    const float* Wq  = (const float*)d_in[3];
    const float* bq  = (const float*)d_in[4];
    const float* Wkv = (const float*)d_in[5];
    const float* bkv = (const float*)d_in[6];
    const float* Wfc = (const float*)d_in[7];
    const float* bfc = (const float*)d_in[8];
    float* out = (float*)d_out;

    cudaFuncSetAttribute(proj_all, cudaFuncAttributeMaxDynamicSharedMemorySize, HGEMM_SMEM);
    cudaFuncSetAttribute(fc_gemm, cudaFuncAttributeMaxDynamicSharedMemorySize, HGEMM_SMEM);
    cudaFuncSetAttribute(attn_h, cudaFuncAttributeMaxDynamicSharedMemorySize, ATTN_SMEM);

    // 1. merged transposes + fused weight convert
    transpose_all<<<dim3(TKK / 32, DD / 32, 2 * NB), 256>>>(q, kv);
    convert_all<<<(DD * DD + 255) / 256, 256>>>(Wq, Wkv, Wfc);

    // 2. merged projections
    proj_all<<<dim3(160, 1, NB), 256, HGEMM_SMEM>>>(bq, bkv);
    // 3. attention
    attn_h<<<dim3(TQ / 128, NB * NH), 256, ATTN_SMEM>>>(kvl);
    // 4. fc
    fc_gemm<<<dim3(DD / 128, TQ / 128, NB), 256, HGEMM_SMEM>>>(bfc, out);
}